// round 2
// baseline (speedup 1.0000x reference)
#include <cuda_runtime.h>
#include <cuda_bf16.h>
#include <cstdint>

// ---------------------------------------------------------------------------
// VectorQuantizerEMA on GB300 (sm_103a)
//
//   k_init    : zero scratch + ||e_k||^2 (double-accumulated)
//   k_argmin  : fused distance screening (packed fp32x2 FFMA) with
//               best/second-best tracking; near-ties rescored EXACTLY in fp64
//               (direct sum (z-e)^2) so argmin == exact-arithmetic argmin.
//               Accumulates counts / embed_sum via vector REDG.
//   k_cluster : EMA cluster size + Laplace smoothing
//   k_embed   : new_embedding = (0.99*embed_avg + 0.01*embed_sum) / smoothed
//   k_quant   : gather z_q + commitment-loss partial sums
//   k_final   : finalize loss scalar
// ---------------------------------------------------------------------------

namespace {
constexpr int Dm   = 64;       // CODEBOOK_DIM
constexpr int Tm   = 4096;
constexpr int Bm   = 32;
constexpr int Km   = 1024;     // CODEBOOK_SIZE
constexpr int Nm   = Bm * Tm;  // 131072 points
constexpr int KC   = 128;      // codes per SMEM chunk (32 KB)
constexpr float DECAY = 0.99f;
constexpr float EPSm  = 1e-5f;
constexpr float TIE_MARGIN = 2e-3f;   // >> screening noise (~2e-5)

constexpr size_t OFF_ZQ   = 0;
constexpr size_t SZ_ZQ    = (size_t)Bm * Dm * Tm;    // 8388608
constexpr size_t OFF_LOSS = SZ_ZQ;                    // 8388608
constexpr size_t OFF_IDX  = SZ_ZQ + 1;                // 8388609
constexpr size_t SZ_FULL  = SZ_ZQ + 1 + (size_t)Nm;  // 8519681
}

// ----------------- device scratch (no allocation allowed) ------------------
__device__ float g_counts[Km];
__device__ __align__(16) float g_embed_sum[Km * Dm];
__device__ float g_c2[Km];
__device__ float g_smoothed[Km];
__device__ __align__(16) float g_new_embedding[Km * Dm];
__device__ int   g_indices[Nm];
__device__ float g_loss;

// ----------------- packed f32x2 helpers ------------------------------------
__device__ __forceinline__ unsigned long long pack2(float x, float y) {
    unsigned long long r;
    asm("mov.b64 %0, {%1, %2};" : "=l"(r) : "f"(x), "f"(y));
    return r;
}
__device__ __forceinline__ void unpack2(unsigned long long v, float& x, float& y) {
    asm("mov.b64 {%0, %1}, %2;" : "=f"(x), "=f"(y) : "l"(v));
}
__device__ __forceinline__ void ffma2(unsigned long long& acc,
                                      unsigned long long a,
                                      unsigned long long b) {
    asm("fma.rn.f32x2 %0, %1, %2, %0;" : "+l"(acc) : "l"(a), "l"(b));
}
__device__ __forceinline__ void red_add_v4(float* p, float a, float b, float c, float d) {
    asm volatile("red.global.add.v4.f32 [%0], {%1, %2, %3, %4};"
                 :: "l"(p), "f"(a), "f"(b), "f"(c), "f"(d) : "memory");
}

// ----------------- k_init: zero scratch + ||e_k||^2 -------------------------
__global__ void k_init(const float* __restrict__ emb) {
    int i = blockIdx.x * blockDim.x + threadIdx.x;
    if (i < Km * Dm) g_embed_sum[i] = 0.0f;
    else if (i < Km * Dm + Km) g_counts[i - Km * Dm] = 0.0f;
    else if (i == Km * Dm + Km) g_loss = 0.0f;

    if (i < Km) {
        const float4* row = reinterpret_cast<const float4*>(emb + (size_t)i * Dm);
        double s = 0.0;
#pragma unroll
        for (int j = 0; j < Dm / 4; j++) {
            float4 e = row[j];
            s += (double)e.x * e.x + (double)e.y * e.y
               + (double)e.z * e.z + (double)e.w * e.w;
        }
        g_c2[i] = (float)s;
    }
}

// ----------------- k_argmin: screening + exact tie rescue -------------------
__global__ void __launch_bounds__(256, 2)
k_argmin(const float* __restrict__ z, const float* __restrict__ emb,
         float* __restrict__ idx_out) {
    __shared__ __align__(16) float s_code[KC * Dm];   // 32 KB
    __shared__ float s_c2[KC];

    const int n = blockIdx.x * 256 + threadIdx.x;     // grid exactly covers Nm
    const int b = n >> 12;                             // n / T
    const int t = n & (Tm - 1);
    const float* zb = z + ((size_t)b * Dm) * Tm + t;

    unsigned long long zu[Dm / 2];
#pragma unroll
    for (int i = 0; i < Dm / 2; i++)
        zu[i] = pack2(zb[(size_t)(2 * i) * Tm], zb[(size_t)(2 * i + 1) * Tm]);

    float best = 3.4e38f;
    float best2 = 3.4e38f;
    int bidx = 0;

    const float4* emb4 = reinterpret_cast<const float4*>(emb);
    float4* s4 = reinterpret_cast<float4*>(s_code);

    for (int chunk = 0; chunk < Km / KC; chunk++) {
        __syncthreads();
        const size_t base4 = (size_t)chunk * KC * (Dm / 4);
#pragma unroll
        for (int j = 0; j < (KC * Dm / 4) / 256; j++)
            s4[threadIdx.x + j * 256] = emb4[base4 + threadIdx.x + j * 256];
        if (threadIdx.x < KC) s_c2[threadIdx.x] = g_c2[chunk * KC + threadIdx.x];
        __syncthreads();

        const ulonglong2* sc = reinterpret_cast<const ulonglong2*>(s_code);
        const int kbase = chunk * KC;
        for (int kk = 0; kk < KC; kk++) {
            unsigned long long a0 = 0ull, a1 = 0ull, a2 = 0ull, a3 = 0ull;
            const ulonglong2* crow = sc + kk * (Dm / 4);
#pragma unroll
            for (int j = 0; j < Dm / 4; j++) {
                ulonglong2 e = crow[j];
                switch ((2 * j) & 3) {
                    case 0: ffma2(a0, zu[2 * j], e.x); ffma2(a1, zu[2 * j + 1], e.y); break;
                    default: ffma2(a2, zu[2 * j], e.x); ffma2(a3, zu[2 * j + 1], e.y); break;
                }
            }
            float f0, f1, f2, f3, f4, f5, f6, f7;
            unpack2(a0, f0, f1); unpack2(a1, f2, f3);
            unpack2(a2, f4, f5); unpack2(a3, f6, f7);
            float dot = ((f0 + f1) + (f2 + f3)) + ((f4 + f5) + (f6 + f7));
            float dist = fmaf(-2.0f, dot, s_c2[kk]);
            if (dist < best) { best2 = best; best = dist; bidx = kbase + kk; }
            else if (dist < best2) { best2 = dist; }
        }
    }

    // Exact rescue: if second-best is within the tie margin, the fp32
    // screening can't be trusted — recompute all distances in fp64
    // (direct form, essentially exact) and take the true argmin.
    if (best2 - best < TIE_MARGIN) {
        double bb = 1e300;
        int bi = 0;
        for (int k = 0; k < Km; k++) {
            const float4* row = reinterpret_cast<const float4*>(emb + (size_t)k * Dm);
            double s = 0.0;
#pragma unroll
            for (int j = 0; j < Dm / 4; j++) {
                float4 e = row[j];
                float x0, x1, x2, x3;
                unpack2(zu[2 * j], x0, x1);
                unpack2(zu[2 * j + 1], x2, x3);
                double d0 = (double)x0 - (double)e.x;
                double d1 = (double)x1 - (double)e.y;
                double d2 = (double)x2 - (double)e.z;
                double d3 = (double)x3 - (double)e.w;
                s += d0 * d0 + d1 * d1 + d2 * d2 + d3 * d3;
            }
            if (s < bb) { bb = s; bi = k; }
        }
        bidx = bi;
    }

    g_indices[n] = bidx;
    if (idx_out) idx_out[n] = (float)bidx;

    atomicAdd(&g_counts[bidx], 1.0f);
    float* dst = g_embed_sum + (size_t)bidx * Dm;
#pragma unroll
    for (int j = 0; j < Dm / 4; j++) {
        float x0, x1, x2, x3;
        unpack2(zu[2 * j], x0, x1);
        unpack2(zu[2 * j + 1], x2, x3);
        red_add_v4(dst + 4 * j, x0, x1, x2, x3);
    }
}

// ----------------- k_cluster: EMA cluster size + smoothing ------------------
__global__ void k_cluster(const float* __restrict__ cluster_size) {
    __shared__ float red[Km];
    int k = threadIdx.x;
    float ncs = fmaf(cluster_size[k], DECAY, (1.0f - DECAY) * g_counts[k]);
    red[k] = ncs;
    __syncthreads();
    for (int s = Km / 2; s > 0; s >>= 1) {
        if (k < s) red[k] += red[k + s];
        __syncthreads();
    }
    float n = red[0];
    float smoothed = __fmul_rn(__fdiv_rn(ncs + EPSm, n + (float)Km * EPSm), n);
    g_smoothed[k] = smoothed;
}

// ----------------- k_embed: updated codebook --------------------------------
__global__ void k_embed(const float* __restrict__ embed_avg) {
    int i = blockIdx.x * blockDim.x + threadIdx.x;   // covers K*D
    float na = fmaf(embed_avg[i], DECAY, (1.0f - DECAY) * g_embed_sum[i]);
    g_new_embedding[i] = __fdiv_rn(na, g_smoothed[i >> 6]);
}

// ----------------- k_quant: gather z_q + loss partials ----------------------
__global__ void __launch_bounds__(256)
k_quant(const float* __restrict__ z, float* __restrict__ out) {
    __shared__ float red[256];
    const int n = blockIdx.x * 256 + threadIdx.x;
    const int b = n >> 12;
    const int t = n & (Tm - 1);
    const float* zb = z + ((size_t)b * Dm) * Tm + t;
    float* ob = out + OFF_ZQ + ((size_t)b * Dm) * Tm + t;

    const int idx = g_indices[n];
    const float4* row = reinterpret_cast<const float4*>(g_new_embedding + (size_t)idx * Dm);

    float acc = 0.0f;
#pragma unroll
    for (int j = 0; j < Dm / 4; j++) {
        float4 e = row[j];
        float zv, df;
        zv = zb[(size_t)(4 * j + 0) * Tm]; ob[(size_t)(4 * j + 0) * Tm] = e.x; df = zv - e.x; acc = fmaf(df, df, acc);
        zv = zb[(size_t)(4 * j + 1) * Tm]; ob[(size_t)(4 * j + 1) * Tm] = e.y; df = zv - e.y; acc = fmaf(df, df, acc);
        zv = zb[(size_t)(4 * j + 2) * Tm]; ob[(size_t)(4 * j + 2) * Tm] = e.z; df = zv - e.z; acc = fmaf(df, df, acc);
        zv = zb[(size_t)(4 * j + 3) * Tm]; ob[(size_t)(4 * j + 3) * Tm] = e.w; df = zv - e.w; acc = fmaf(df, df, acc);
    }

    red[threadIdx.x] = acc;
    __syncthreads();
    for (int s = 128; s > 0; s >>= 1) {
        if (threadIdx.x < s) red[threadIdx.x] += red[threadIdx.x + s];
        __syncthreads();
    }
    if (threadIdx.x == 0) atomicAdd(&g_loss, red[0]);
}

// ----------------- k_final: loss scalar -------------------------------------
__global__ void k_final(float* __restrict__ loss_out) {
    loss_out[0] = 0.25f * __fdiv_rn(g_loss, (float)((size_t)Nm * Dm));
}

// ----------------- launch ----------------------------------------------------
extern "C" void kernel_launch(void* const* d_in, const int* in_sizes, int n_in,
                              void* d_out, int out_size) {
    const float* z    = (const float*)d_in[0];   // [32, 64, 4096]
    const float* emb  = (const float*)d_in[1];   // [1024, 64]
    const float* cs   = (const float*)d_in[2];   // [1024]
    const float* avg  = (const float*)d_in[3];   // [1024, 64]
    float* out = (float*)d_out;

    const bool full = ((size_t)out_size >= SZ_FULL);
    float* idx_out  = full ? out + OFF_IDX  : nullptr;
    float* loss_out = full ? out + OFF_LOSS : nullptr;

    k_init<<<(Km * Dm + Km + 1 + 255) / 256, 256>>>(emb);
    k_argmin<<<Nm / 256, 256>>>(z, emb, idx_out);
    k_cluster<<<1, Km>>>(cs);
    k_embed<<<(Km * Dm) / 1024, 1024>>>(avg);
    k_quant<<<Nm / 256, 256>>>(z, out);
    if (loss_out) k_final<<<1, 1>>>(loss_out);
}

// round 4
// speedup vs baseline: 10.0047x; 10.0047x over previous
#include <cuda_runtime.h>
#include <cuda_bf16.h>
#include <cstdint>

// ---------------------------------------------------------------------------
// VectorQuantizerEMA on GB300 (sm_103a) — tiled f32x2 distance GEMM + argmin
// ---------------------------------------------------------------------------

namespace {
constexpr int Dm   = 64;
constexpr int Tm   = 4096;
constexpr int Bm   = 32;
constexpr int Km   = 1024;
constexpr int Nm   = Bm * Tm;          // 131072 points
constexpr int PTS  = 64;               // points per block
constexpr int KC   = 128;              // codes per chunk
constexpr float DECAY = 0.99f;
constexpr float EPSm  = 1e-5f;
constexpr float TIE_MARGIN = 2e-3f;

constexpr size_t OFF_ZQ   = 0;
constexpr size_t SZ_ZQ    = (size_t)Bm * Dm * Tm;
constexpr size_t OFF_LOSS = SZ_ZQ;
constexpr size_t OFF_IDX  = SZ_ZQ + 1;
constexpr size_t SZ_FULL  = SZ_ZQ + 1 + (size_t)Nm;
}

// ----------------- device scratch ------------------------------------------
__device__ float g_counts[Km];
__device__ __align__(16) float g_embed_sum[Km * Dm];
__device__ float g_c2[Km];
__device__ float g_smoothed[Km];
__device__ __align__(16) float g_new_embedding[Km * Dm];
__device__ int   g_indices[Nm];
__device__ float g_loss;

// ----------------- helpers --------------------------------------------------
__device__ __forceinline__ unsigned long long pack2(float x, float y) {
    unsigned long long r;
    asm("mov.b64 %0, {%1, %2};" : "=l"(r) : "f"(x), "f"(y));
    return r;
}
__device__ __forceinline__ void unpack2(unsigned long long v, float& x, float& y) {
    asm("mov.b64 {%0, %1}, %2;" : "=f"(x), "=f"(y) : "l"(v));
}
__device__ __forceinline__ void ffma2(unsigned long long& acc,
                                      unsigned long long a,
                                      unsigned long long b) {
    asm("fma.rn.f32x2 %0, %1, %2, %0;" : "+l"(acc) : "l"(a), "l"(b));
}
__device__ __forceinline__ void red_add_v4(float* p, float a, float b, float c, float d) {
    asm volatile("red.global.add.v4.f32 [%0], {%1, %2, %3, %4};"
                 :: "l"(p), "f"(a), "f"(b), "f"(c), "f"(d) : "memory");
}

// ----------------- tiny init kernels (also position argmin for ncu) ---------
__global__ void k_zero1() {
    int i = blockIdx.x * blockDim.x + threadIdx.x;
    g_embed_sum[i] = 0.0f;                          // first half: grid covers 32768
}
__global__ void k_zero2() {
    int i = blockIdx.x * blockDim.x + threadIdx.x;
    if (i < Km * Dm / 2) g_embed_sum[Km * Dm / 2 + i] = 0.0f;
    else if (i < Km * Dm / 2 + Km) g_counts[i - Km * Dm / 2] = 0.0f;
    else if (i == Km * Dm / 2 + Km) g_loss = 0.0f;
}
__global__ void k_c2(const float* __restrict__ emb) {
    int i = blockIdx.x * blockDim.x + threadIdx.x;  // 1024 threads
    const float4* row = reinterpret_cast<const float4*>(emb + (size_t)i * Dm);
    double s = 0.0;
#pragma unroll
    for (int j = 0; j < Dm / 4; j++) {
        float4 e = row[j];
        s += (double)e.x * e.x + (double)e.y * e.y
           + (double)e.z * e.z + (double)e.w * e.w;
    }
    g_c2[i] = (float)s;
}

// ----------------- k_argmin: tiled screening + parallel fp64 rescue ---------
struct SmemT {
    unsigned long long z[32][64];     // 16KB : dim-pairs x points
    unsigned long long e[16][128];    // 16KB : dim-pairs (half-D) x codes
    float c2[KC];                     // 0.5KB
    union {
        struct { float best[16][64]; float best2[16][64]; int idx[16][64]; } m; // 12KB
        struct { double rb[256]; int ri[256]; } r;                               // 3KB
    } u;
    int flag[PTS];
    int fidx[PTS];
};

__global__ void __launch_bounds__(256)
k_argmin(const float* __restrict__ z, const float* __restrict__ emb,
         float* __restrict__ idx_out) {
    __shared__ SmemT s;
    const int tid = threadIdx.x;
    const int tx = tid & 15;          // point group: pts tx*4 .. tx*4+3
    const int ty = tid >> 4;          // code group: codes ty*8 .. ty*8+7
    const int n0 = blockIdx.x * PTS;
    const int b  = n0 >> 12;
    const int t0 = n0 & (Tm - 1);
    const float* zb = z + ((size_t)b * Dm) * Tm + t0;
    const float4* emb4 = reinterpret_cast<const float4*>(emb);

    // ---- load z tile: 2048 u64, 8 per thread, coalesced along t ----
#pragma unroll
    for (int e8 = 0; e8 < 8; ++e8) {
        int m  = tid + e8 * 256;
        int dp = m >> 6, pt = m & 63;
        float x0 = zb[(size_t)(2 * dp) * Tm + pt];
        float x1 = zb[(size_t)(2 * dp + 1) * Tm + pt];
        s.z[dp][pt] = pack2(x0, x1);
    }

    unsigned long long acc[4][8];
#pragma unroll
    for (int i = 0; i < 4; ++i)
#pragma unroll
        for (int j = 0; j < 8; ++j) acc[i][j] = 0ull;

    float best[4], best2[4];
    int bidx[4];
#pragma unroll
    for (int i = 0; i < 4; ++i) { best[i] = 3.4e38f; best2[i] = 3.4e38f; bidx[i] = 0; }

    for (int kc = 0; kc < Km / KC; ++kc) {
#pragma unroll
        for (int half = 0; half < 2; ++half) {
            __syncthreads();
            // load e half-tile: codes kc*128.., dims half*32..+31 (packed pairs)
#pragma unroll
            for (int q = 0; q < 4; ++q) {
                int m = tid + q * 256;          // 0..1023
                int k = m >> 3, f = m & 7;
                float4 e4 = emb4[(size_t)(kc * KC + k) * (Dm / 4) + half * 8 + f];
                s.e[f * 2][k]     = pack2(e4.x, e4.y);
                s.e[f * 2 + 1][k] = pack2(e4.z, e4.w);
            }
            if (half == 0 && tid < KC) s.c2[tid] = g_c2[kc * KC + tid];
            __syncthreads();

            const int dbase = half * 16;
#pragma unroll 4
            for (int dp = 0; dp < 16; ++dp) {
                unsigned long long zr[4], er[8];
                const ulonglong2* zp =
                    reinterpret_cast<const ulonglong2*>(&s.z[dbase + dp][tx * 4]);
                ulonglong2 za = zp[0], zc = zp[1];
                zr[0] = za.x; zr[1] = za.y; zr[2] = zc.x; zr[3] = zc.y;
                const ulonglong2* ep =
                    reinterpret_cast<const ulonglong2*>(&s.e[dp][ty * 8]);
#pragma unroll
                for (int jj = 0; jj < 4; ++jj) {
                    ulonglong2 ee = ep[jj];
                    er[2 * jj] = ee.x; er[2 * jj + 1] = ee.y;
                }
#pragma unroll
                for (int i = 0; i < 4; ++i)
#pragma unroll
                    for (int j = 0; j < 8; ++j) ffma2(acc[i][j], zr[i], er[j]);
            }
        }

        // ---- fold this chunk's dots into running best/best2 ----
#pragma unroll
        for (int i = 0; i < 4; ++i)
#pragma unroll
            for (int j = 0; j < 8; ++j) {
                float se, so;
                unpack2(acc[i][j], se, so);
                float dot  = se + so;
                float dist = fmaf(-2.0f, dot, s.c2[ty * 8 + j]);
                int   k    = kc * KC + ty * 8 + j;
                if (dist < best[i]) { best2[i] = best[i]; best[i] = dist; bidx[i] = k; }
                else if (dist < best2[i]) best2[i] = dist;
                acc[i][j] = 0ull;
            }
    }

    // ---- cross-thread merge per point ----
#pragma unroll
    for (int i = 0; i < 4; ++i) {
        int pt = tx * 4 + i;
        s.u.m.best[ty][pt]  = best[i];
        s.u.m.best2[ty][pt] = best2[i];
        s.u.m.idx[ty][pt]   = bidx[i];
    }
    __syncthreads();
    if (tid < PTS) {
        float b1 = 3.4e38f, b2 = 3.4e38f;
        int bi = 0;
        for (int t2 = 0; t2 < 16; ++t2) {     // ascending ty == ascending code idx
            float cb  = s.u.m.best[t2][tid];
            float cb2 = s.u.m.best2[t2][tid];
            int   ci  = s.u.m.idx[t2][tid];
            if (cb < b1) { b2 = fminf(b1, cb2); b1 = cb; bi = ci; }
            else b2 = fminf(b2, cb);
        }
        s.fidx[tid] = bi;
        s.flag[tid] = (b2 - b1 < TIE_MARGIN) ? 1 : 0;
    }
    __syncthreads();

    // ---- exact fp64 rescue for near-ties (block-parallel, rare) ----
    for (int pt = 0; pt < PTS; ++pt) {
        if (!s.flag[pt]) continue;            // uniform branch
        double bb = 1e300;
        int bi2 = 0;
#pragma unroll 1
        for (int q = 0; q < 4; ++q) {
            int k = tid * 4 + q;
            const float4* row = emb4 + (size_t)k * (Dm / 4);
            double ssum = 0.0;
#pragma unroll
            for (int jj = 0; jj < Dm / 4; ++jj) {
                float4 e = row[jj];
                float x0, x1, x2, x3;
                unpack2(s.z[2 * jj][pt], x0, x1);
                unpack2(s.z[2 * jj + 1][pt], x2, x3);
                double d0 = (double)x0 - e.x, d1 = (double)x1 - e.y;
                double d2 = (double)x2 - e.z, d3 = (double)x3 - e.w;
                ssum += d0 * d0 + d1 * d1 + d2 * d2 + d3 * d3;
            }
            if (ssum < bb) { bb = ssum; bi2 = k; }
        }
        s.u.r.rb[tid] = bb; s.u.r.ri[tid] = bi2;
        __syncthreads();
        for (int st = 128; st > 0; st >>= 1) {
            if (tid < st) {
                double o = s.u.r.rb[tid + st]; int oi = s.u.r.ri[tid + st];
                double m0 = s.u.r.rb[tid];     int mi = s.u.r.ri[tid];
                if (o < m0 || (o == m0 && oi < mi)) { s.u.r.rb[tid] = o; s.u.r.ri[tid] = oi; }
            }
            __syncthreads();
        }
        if (tid == 0) s.fidx[pt] = s.u.r.ri[0];
        __syncthreads();
    }

    // ---- per-point outputs + EMA segment sums ----
    if (tid < PTS) {
        int pt = tid, n = n0 + pt, idx = s.fidx[pt];
        g_indices[n] = idx;
        if (idx_out) idx_out[n] = (float)idx;
        atomicAdd(&g_counts[idx], 1.0f);
        float* dst = g_embed_sum + (size_t)idx * Dm;
#pragma unroll
        for (int j = 0; j < Dm / 4; ++j) {
            float x0, x1, x2, x3;
            unpack2(s.z[2 * j][pt], x0, x1);
            unpack2(s.z[2 * j + 1][pt], x2, x3);
            red_add_v4(dst + 4 * j, x0, x1, x2, x3);
        }
    }
}

// ----------------- k_cluster ------------------------------------------------
__global__ void k_cluster(const float* __restrict__ cluster_size) {
    __shared__ float red[Km];
    int k = threadIdx.x;
    float ncs = fmaf(cluster_size[k], DECAY, (1.0f - DECAY) * g_counts[k]);
    red[k] = ncs;
    __syncthreads();
    for (int s = Km / 2; s > 0; s >>= 1) {
        if (k < s) red[k] += red[k + s];
        __syncthreads();
    }
    float n = red[0];
    g_smoothed[k] = __fmul_rn(__fdiv_rn(ncs + EPSm, n + (float)Km * EPSm), n);
}

// ----------------- k_embed --------------------------------------------------
__global__ void k_embed(const float* __restrict__ embed_avg) {
    int i = blockIdx.x * blockDim.x + threadIdx.x;
    float na = fmaf(embed_avg[i], DECAY, (1.0f - DECAY) * g_embed_sum[i]);
    g_new_embedding[i] = __fdiv_rn(na, g_smoothed[i >> 6]);
}

// ----------------- k_quant --------------------------------------------------
__global__ void __launch_bounds__(256)
k_quant(const float* __restrict__ z, float* __restrict__ out) {
    __shared__ float red[256];
    const int n = blockIdx.x * 256 + threadIdx.x;
    const int b = n >> 12;
    const int t = n & (Tm - 1);
    const float* zb = z + ((size_t)b * Dm) * Tm + t;
    float* ob = out + OFF_ZQ + ((size_t)b * Dm) * Tm + t;

    const int idx = g_indices[n];
    const float4* row = reinterpret_cast<const float4*>(g_new_embedding + (size_t)idx * Dm);

    float acc = 0.0f;
#pragma unroll
    for (int j = 0; j < Dm / 4; j++) {
        float4 e = row[j];
        float zv, df;
        zv = zb[(size_t)(4 * j + 0) * Tm]; ob[(size_t)(4 * j + 0) * Tm] = e.x; df = zv - e.x; acc = fmaf(df, df, acc);
        zv = zb[(size_t)(4 * j + 1) * Tm]; ob[(size_t)(4 * j + 1) * Tm] = e.y; df = zv - e.y; acc = fmaf(df, df, acc);
        zv = zb[(size_t)(4 * j + 2) * Tm]; ob[(size_t)(4 * j + 2) * Tm] = e.z; df = zv - e.z; acc = fmaf(df, df, acc);
        zv = zb[(size_t)(4 * j + 3) * Tm]; ob[(size_t)(4 * j + 3) * Tm] = e.w; df = zv - e.w; acc = fmaf(df, df, acc);
    }

    red[threadIdx.x] = acc;
    __syncthreads();
    for (int st = 128; st > 0; st >>= 1) {
        if (threadIdx.x < st) red[threadIdx.x] += red[threadIdx.x + st];
        __syncthreads();
    }
    if (threadIdx.x == 0) atomicAdd(&g_loss, red[0]);
}

// ----------------- k_final --------------------------------------------------
__global__ void k_final(float* __restrict__ loss_out) {
    loss_out[0] = 0.25f * __fdiv_rn(g_loss, (float)((size_t)Nm * Dm));
}

// ----------------- launch ----------------------------------------------------
extern "C" void kernel_launch(void* const* d_in, const int* in_sizes, int n_in,
                              void* d_out, int out_size) {
    const float* z    = (const float*)d_in[0];
    const float* emb  = (const float*)d_in[1];
    const float* cs   = (const float*)d_in[2];
    const float* avg  = (const float*)d_in[3];
    float* out = (float*)d_out;

    const bool full = ((size_t)out_size >= SZ_FULL);
    float* idx_out  = full ? out + OFF_IDX  : nullptr;
    float* loss_out = full ? out + OFF_LOSS : nullptr;

    k_zero1<<<Km * Dm / 2 / 1024, 1024>>>();
    k_zero2<<<(Km * Dm / 2 + Km + 1 + 1023) / 1024, 1024>>>();
    k_c2<<<Km / 256, 256>>>(emb);
    k_argmin<<<Nm / PTS, 256>>>(z, emb, idx_out);      // launch index 3
    k_cluster<<<1, Km>>>(cs);
    k_embed<<<(Km * Dm) / 1024, 1024>>>(avg);
    k_quant<<<Nm / 256, 256>>>(z, out);
    if (loss_out) k_final<<<1, 1>>>(loss_out);
}

// round 6
// speedup vs baseline: 10.5675x; 1.0563x over previous
#include <cuda_runtime.h>
#include <cuda_bf16.h>
#include <cstdint>

// ---------------------------------------------------------------------------
// VectorQuantizerEMA on GB300 (sm_103a) — tiled f32x2 distance GEMM + argmin
// R6: fixed z-tile swizzle READ path. Data for points (p0,p1) and (p2,p3) of
// thread tx live at element offsets zsw(4tx) and zsw(4tx+2); reading those two
// 16B pairs (instead of one contiguous 32B span) restores correctness AND
// realizes the 2-phase (minimum) LDS pattern the swizzle was built for.
// ---------------------------------------------------------------------------

namespace {
constexpr int Dm   = 64;
constexpr int Tm   = 4096;
constexpr int Bm   = 32;
constexpr int Km   = 1024;
constexpr int Nm   = Bm * Tm;          // 131072 points
constexpr int PTS  = 64;               // points per block
constexpr int KC   = 128;              // codes per chunk
constexpr float DECAY = 0.99f;
constexpr float EPSm  = 1e-5f;
constexpr float TIE_MARGIN = 2e-3f;

constexpr size_t OFF_ZQ   = 0;
constexpr size_t SZ_ZQ    = (size_t)Bm * Dm * Tm;
constexpr size_t OFF_LOSS = SZ_ZQ;
constexpr size_t OFF_IDX  = SZ_ZQ + 1;
constexpr size_t SZ_FULL  = SZ_ZQ + 1 + (size_t)Nm;
}

// ----------------- device scratch ------------------------------------------
__device__ float g_counts[Km];
__device__ __align__(16) float g_embed_sum[Km * Dm];
__device__ float g_c2[Km];
__device__ float g_smoothed[Km];
__device__ __align__(16) float g_new_embedding[Km * Dm];
__device__ int   g_indices[Nm];
__device__ float g_loss;

// ----------------- helpers --------------------------------------------------
__device__ __forceinline__ unsigned long long pack2(float x, float y) {
    unsigned long long r;
    asm("mov.b64 %0, {%1, %2};" : "=l"(r) : "f"(x), "f"(y));
    return r;
}
__device__ __forceinline__ void unpack2(unsigned long long v, float& x, float& y) {
    asm("mov.b64 {%0, %1}, %2;" : "=f"(x), "=f"(y) : "l"(v));
}
__device__ __forceinline__ void ffma2(unsigned long long& acc,
                                      unsigned long long a,
                                      unsigned long long b) {
    asm("fma.rn.f32x2 %0, %1, %2, %0;" : "+l"(acc) : "l"(a), "l"(b));
}
__device__ __forceinline__ void red_add_v4(float* p, float a, float b, float c, float d) {
    asm volatile("red.global.add.v4.f32 [%0], {%1, %2, %3, %4};"
                 :: "l"(p), "f"(a), "f"(b), "f"(c), "f"(d) : "memory");
}
// element-level swizzle of the z tile: swaps the two 16B halves of each 32B
// point-chunk when bit4 of the element index is set. Bijective; 16B pairs
// stay 16B-aligned. Readers locate pair (p,p+1) at element zsw(p).
__device__ __forceinline__ int zsw(int pt) { return pt ^ ((pt & 16) >> 3); }

// ----------------- tiny init kernels ----------------------------------------
__global__ void k_zero1() {
    int i = blockIdx.x * blockDim.x + threadIdx.x;
    g_embed_sum[i] = 0.0f;
}
__global__ void k_zero2() {
    int i = blockIdx.x * blockDim.x + threadIdx.x;
    if (i < Km * Dm / 2) g_embed_sum[Km * Dm / 2 + i] = 0.0f;
    else if (i < Km * Dm / 2 + Km) g_counts[i - Km * Dm / 2] = 0.0f;
    else if (i == Km * Dm / 2 + Km) g_loss = 0.0f;
}
__global__ void k_c2(const float* __restrict__ emb) {
    int i = blockIdx.x * blockDim.x + threadIdx.x;
    const float4* row = reinterpret_cast<const float4*>(emb + (size_t)i * Dm);
    double s = 0.0;
#pragma unroll
    for (int j = 0; j < Dm / 4; j++) {
        float4 e = row[j];
        s += (double)e.x * e.x + (double)e.y * e.y
           + (double)e.z * e.z + (double)e.w * e.w;
    }
    g_c2[i] = (float)s;
}

// ----------------- k_argmin: tiled screening + parallel fp64 rescue ---------
struct SmemT {
    unsigned long long z[32][64];     // 16KB : dim-pairs x points (swizzled)
    unsigned long long e[16][128];    // 16KB : dim-pairs (half-D) x codes
    float c2[KC];                     // 0.5KB
    union {
        struct { float best[16][64]; float best2[16][64]; int idx[16][64]; } m;
        struct { double rb[256]; int ri[256]; } r;
    } u;
    int flag[PTS];
    int fidx[PTS];
};

__global__ void __launch_bounds__(256)
k_argmin(const float* __restrict__ z, const float* __restrict__ emb,
         float* __restrict__ idx_out) {
    __shared__ SmemT s;
    const int tid = threadIdx.x;
    const int tx = tid & 15;          // point group: pts tx*4 .. tx*4+3
    const int ty = tid >> 4;          // code group: codes ty*8 .. ty*8+7
    const int n0 = blockIdx.x * PTS;
    const int b  = n0 >> 12;
    const int t0 = n0 & (Tm - 1);
    const float* zb = z + ((size_t)b * Dm) * Tm + t0;
    const float4* emb4 = reinterpret_cast<const float4*>(emb);

    // ---- load z tile (coalesced along t; swizzled store) ----
#pragma unroll
    for (int e8 = 0; e8 < 8; ++e8) {
        int m  = tid + e8 * 256;
        int dp = m >> 6, pt = m & 63;
        float x0 = zb[(size_t)(2 * dp) * Tm + pt];
        float x1 = zb[(size_t)(2 * dp + 1) * Tm + pt];
        s.z[dp][zsw(pt)] = pack2(x0, x1);
    }

    unsigned long long acc[4][8];
#pragma unroll
    for (int i = 0; i < 4; ++i)
#pragma unroll
        for (int j = 0; j < 8; ++j) acc[i][j] = 0ull;

    float best[4], best2[4];
    int bidx[4];
#pragma unroll
    for (int i = 0; i < 4; ++i) { best[i] = 3.4e38f; best2[i] = 3.4e38f; bidx[i] = 0; }

    const int e0 = zsw(tx * 4);       // element holding (p0,p1)
    const int e1 = zsw(tx * 4 + 2);   // element holding (p2,p3)

    for (int kc = 0; kc < Km / KC; ++kc) {
#pragma unroll
        for (int half = 0; half < 2; ++half) {
            __syncthreads();
#pragma unroll
            for (int q = 0; q < 4; ++q) {
                int m = tid + q * 256;          // 0..1023
                int k = m >> 3, f = m & 7;
                float4 e4 = emb4[(size_t)(kc * KC + k) * (Dm / 4) + half * 8 + f];
                s.e[f * 2][k]     = pack2(e4.x, e4.y);
                s.e[f * 2 + 1][k] = pack2(e4.z, e4.w);
            }
            if (half == 0 && tid < KC) s.c2[tid] = g_c2[kc * KC + tid];
            __syncthreads();

            const int dbase = half * 16;
#pragma unroll 4
            for (int dp = 0; dp < 16; ++dp) {
                unsigned long long zr[4], er[8];
                ulonglong2 za = *reinterpret_cast<const ulonglong2*>(&s.z[dbase + dp][e0]);
                ulonglong2 zc = *reinterpret_cast<const ulonglong2*>(&s.z[dbase + dp][e1]);
                zr[0] = za.x; zr[1] = za.y; zr[2] = zc.x; zr[3] = zc.y;
                const ulonglong2* ep =
                    reinterpret_cast<const ulonglong2*>(&s.e[dp][ty * 8]);
#pragma unroll
                for (int jj = 0; jj < 4; ++jj) {
                    ulonglong2 ee = ep[jj];
                    er[2 * jj] = ee.x; er[2 * jj + 1] = ee.y;
                }
#pragma unroll
                for (int i = 0; i < 4; ++i)
#pragma unroll
                    for (int j = 0; j < 8; ++j) ffma2(acc[i][j], zr[i], er[j]);
            }
        }

        // ---- fold this chunk's dots into running best/best2 ----
#pragma unroll
        for (int i = 0; i < 4; ++i)
#pragma unroll
            for (int j = 0; j < 8; ++j) {
                float se, so;
                unpack2(acc[i][j], se, so);
                float dot  = se + so;
                float dist = fmaf(-2.0f, dot, s.c2[ty * 8 + j]);
                int   k    = kc * KC + ty * 8 + j;
                if (dist < best[i]) { best2[i] = best[i]; best[i] = dist; bidx[i] = k; }
                else if (dist < best2[i]) best2[i] = dist;
                acc[i][j] = 0ull;
            }
    }

    // ---- cross-thread merge per point ----
#pragma unroll
    for (int i = 0; i < 4; ++i) {
        int pt = tx * 4 + i;
        s.u.m.best[ty][pt]  = best[i];
        s.u.m.best2[ty][pt] = best2[i];
        s.u.m.idx[ty][pt]   = bidx[i];
    }
    __syncthreads();
    if (tid < PTS) {
        float b1 = 3.4e38f, b2 = 3.4e38f;
        int bi = 0;
        for (int t2 = 0; t2 < 16; ++t2) {     // ascending ty == ascending code idx
            float cb  = s.u.m.best[t2][tid];
            float cb2 = s.u.m.best2[t2][tid];
            int   ci  = s.u.m.idx[t2][tid];
            if (cb < b1) { b2 = fminf(b1, cb2); b1 = cb; bi = ci; }
            else b2 = fminf(b2, cb);
        }
        s.fidx[tid] = bi;
        s.flag[tid] = (b2 - b1 < TIE_MARGIN) ? 1 : 0;
    }
    __syncthreads();

    // ---- exact fp64 rescue for near-ties (block-parallel, rare) ----
    for (int pt = 0; pt < PTS; ++pt) {
        if (!s.flag[pt]) continue;            // uniform branch
        double bb = 1e300;
        int bi2 = 0;
#pragma unroll 1
        for (int q = 0; q < 4; ++q) {
            int k = tid * 4 + q;
            const float4* row = emb4 + (size_t)k * (Dm / 4);
            double ssum = 0.0;
#pragma unroll
            for (int jj = 0; jj < Dm / 4; ++jj) {
                float4 e = row[jj];
                float x0, x1, x2, x3;
                unpack2(s.z[2 * jj][zsw(pt)], x0, x1);
                unpack2(s.z[2 * jj + 1][zsw(pt)], x2, x3);
                double d0 = (double)x0 - e.x, d1 = (double)x1 - e.y;
                double d2 = (double)x2 - e.z, d3 = (double)x3 - e.w;
                ssum += d0 * d0 + d1 * d1 + d2 * d2 + d3 * d3;
            }
            if (ssum < bb) { bb = ssum; bi2 = k; }
        }
        s.u.r.rb[tid] = bb; s.u.r.ri[tid] = bi2;
        __syncthreads();
        for (int st = 128; st > 0; st >>= 1) {
            if (tid < st) {
                double o = s.u.r.rb[tid + st]; int oi = s.u.r.ri[tid + st];
                double m0 = s.u.r.rb[tid];     int mi = s.u.r.ri[tid];
                if (o < m0 || (o == m0 && oi < mi)) { s.u.r.rb[tid] = o; s.u.r.ri[tid] = oi; }
            }
            __syncthreads();
        }
        if (tid == 0) s.fidx[pt] = s.u.r.ri[0];
        __syncthreads();
    }

    // ---- per-point outputs + EMA segment sums ----
    if (tid < PTS) {
        int pt = tid, n = n0 + pt, idx = s.fidx[pt];
        g_indices[n] = idx;
        if (idx_out) idx_out[n] = (float)idx;
        atomicAdd(&g_counts[idx], 1.0f);
        float* dst = g_embed_sum + (size_t)idx * Dm;
#pragma unroll
        for (int j = 0; j < Dm / 4; ++j) {
            float x0, x1, x2, x3;
            unpack2(s.z[2 * j][zsw(pt)], x0, x1);
            unpack2(s.z[2 * j + 1][zsw(pt)], x2, x3);
            red_add_v4(dst + 4 * j, x0, x1, x2, x3);
        }
    }
}

// ----------------- k_cluster ------------------------------------------------
__global__ void k_cluster(const float* __restrict__ cluster_size) {
    __shared__ float red[Km];
    int k = threadIdx.x;
    float ncs = fmaf(cluster_size[k], DECAY, (1.0f - DECAY) * g_counts[k]);
    red[k] = ncs;
    __syncthreads();
    for (int s = Km / 2; s > 0; s >>= 1) {
        if (k < s) red[k] += red[k + s];
        __syncthreads();
    }
    float n = red[0];
    g_smoothed[k] = __fmul_rn(__fdiv_rn(ncs + EPSm, n + (float)Km * EPSm), n);
}

// ----------------- k_embed --------------------------------------------------
__global__ void k_embed(const float* __restrict__ embed_avg) {
    int i = blockIdx.x * blockDim.x + threadIdx.x;
    float na = fmaf(embed_avg[i], DECAY, (1.0f - DECAY) * g_embed_sum[i]);
    g_new_embedding[i] = __fdiv_rn(na, g_smoothed[i >> 6]);
}

// ----------------- k_quant --------------------------------------------------
__global__ void __launch_bounds__(256)
k_quant(const float* __restrict__ z, float* __restrict__ out) {
    __shared__ float red[256];
    const int n = blockIdx.x * 256 + threadIdx.x;
    const int b = n >> 12;
    const int t = n & (Tm - 1);
    const float* zb = z + ((size_t)b * Dm) * Tm + t;
    float* ob = out + OFF_ZQ + ((size_t)b * Dm) * Tm + t;

    const int idx = g_indices[n];
    const float4* row = reinterpret_cast<const float4*>(g_new_embedding + (size_t)idx * Dm);

    float acc = 0.0f;
#pragma unroll
    for (int j = 0; j < Dm / 4; j++) {
        float4 e = row[j];
        float zv, df;
        zv = zb[(size_t)(4 * j + 0) * Tm]; ob[(size_t)(4 * j + 0) * Tm] = e.x; df = zv - e.x; acc = fmaf(df, df, acc);
        zv = zb[(size_t)(4 * j + 1) * Tm]; ob[(size_t)(4 * j + 1) * Tm] = e.y; df = zv - e.y; acc = fmaf(df, df, acc);
        zv = zb[(size_t)(4 * j + 2) * Tm]; ob[(size_t)(4 * j + 2) * Tm] = e.z; df = zv - e.z; acc = fmaf(df, df, acc);
        zv = zb[(size_t)(4 * j + 3) * Tm]; ob[(size_t)(4 * j + 3) * Tm] = e.w; df = zv - e.w; acc = fmaf(df, df, acc);
    }

    red[threadIdx.x] = acc;
    __syncthreads();
    for (int st = 128; st > 0; st >>= 1) {
        if (threadIdx.x < st) red[threadIdx.x] += red[threadIdx.x + st];
        __syncthreads();
    }
    if (threadIdx.x == 0) atomicAdd(&g_loss, red[0]);
}

// ----------------- k_final --------------------------------------------------
__global__ void k_final(float* __restrict__ loss_out) {
    loss_out[0] = 0.25f * __fdiv_rn(g_loss, (float)((size_t)Nm * Dm));
}

// ----------------- launch ----------------------------------------------------
extern "C" void kernel_launch(void* const* d_in, const int* in_sizes, int n_in,
                              void* d_out, int out_size) {
    const float* z    = (const float*)d_in[0];
    const float* emb  = (const float*)d_in[1];
    const float* cs   = (const float*)d_in[2];
    const float* avg  = (const float*)d_in[3];
    float* out = (float*)d_out;

    const bool full = ((size_t)out_size >= SZ_FULL);
    float* idx_out  = full ? out + OFF_IDX  : nullptr;
    float* loss_out = full ? out + OFF_LOSS : nullptr;

    k_zero1<<<Km * Dm / 2 / 1024, 1024>>>();
    k_zero2<<<(Km * Dm / 2 + Km + 1 + 1023) / 1024, 1024>>>();
    k_c2<<<Km / 256, 256>>>(emb);
    k_argmin<<<Nm / PTS, 256>>>(z, emb, idx_out);      // launch index 3
    k_cluster<<<1, Km>>>(cs);
    k_embed<<<(Km * Dm) / 1024, 1024>>>(avg);
    k_quant<<<Nm / 256, 256>>>(z, out);
    if (loss_out) k_final<<<1, 1>>>(loss_out);
}

// round 8
// speedup vs baseline: 10.8679x; 1.0284x over previous
#include <cuda_runtime.h>
#include <cuda_bf16.h>
#include <cstdint>

// ---------------------------------------------------------------------------
// VectorQuantizerEMA on GB300 (sm_103a) — tiled f32x2 distance GEMM + argmin
// R7: occupancy fix. 2 pts x 8 codes per thread (32 acc regs), <=128 regs,
// 2 blocks/SM (16 warps). z tile needs no swizzle (1 LDS.128, 2-phase min).
// ---------------------------------------------------------------------------

namespace {
constexpr int Dm   = 64;
constexpr int Tm   = 4096;
constexpr int Bm   = 32;
constexpr int Km   = 1024;
constexpr int Nm   = Bm * Tm;          // 131072 points
constexpr int PTS  = 32;               // points per block
constexpr int KC   = 128;              // codes per chunk
constexpr float DECAY = 0.99f;
constexpr float EPSm  = 1e-5f;
constexpr float TIE_MARGIN = 2e-3f;

constexpr size_t OFF_ZQ   = 0;
constexpr size_t SZ_ZQ    = (size_t)Bm * Dm * Tm;
constexpr size_t OFF_LOSS = SZ_ZQ;
constexpr size_t OFF_IDX  = SZ_ZQ + 1;
constexpr size_t SZ_FULL  = SZ_ZQ + 1 + (size_t)Nm;
}

// ----------------- device scratch ------------------------------------------
__device__ float g_counts[Km];
__device__ __align__(16) float g_embed_sum[Km * Dm];
__device__ float g_c2[Km];
__device__ float g_smoothed[Km];
__device__ __align__(16) float g_new_embedding[Km * Dm];
__device__ int   g_indices[Nm];
__device__ float g_loss;

// ----------------- helpers --------------------------------------------------
__device__ __forceinline__ unsigned long long pack2(float x, float y) {
    unsigned long long r;
    asm("mov.b64 %0, {%1, %2};" : "=l"(r) : "f"(x), "f"(y));
    return r;
}
__device__ __forceinline__ void unpack2(unsigned long long v, float& x, float& y) {
    asm("mov.b64 {%0, %1}, %2;" : "=f"(x), "=f"(y) : "l"(v));
}
__device__ __forceinline__ void ffma2(unsigned long long& acc,
                                      unsigned long long a,
                                      unsigned long long b) {
    asm("fma.rn.f32x2 %0, %1, %2, %0;" : "+l"(acc) : "l"(a), "l"(b));
}
__device__ __forceinline__ void red_add_v4(float* p, float a, float b, float c, float d) {
    asm volatile("red.global.add.v4.f32 [%0], {%1, %2, %3, %4};"
                 :: "l"(p), "f"(a), "f"(b), "f"(c), "f"(d) : "memory");
}

// ----------------- tiny init kernels ----------------------------------------
__global__ void k_zero1() {
    int i = blockIdx.x * blockDim.x + threadIdx.x;
    g_embed_sum[i] = 0.0f;
}
__global__ void k_zero2() {
    int i = blockIdx.x * blockDim.x + threadIdx.x;
    if (i < Km * Dm / 2) g_embed_sum[Km * Dm / 2 + i] = 0.0f;
    else if (i < Km * Dm / 2 + Km) g_counts[i - Km * Dm / 2] = 0.0f;
    else if (i == Km * Dm / 2 + Km) g_loss = 0.0f;
}
__global__ void k_c2(const float* __restrict__ emb) {
    int i = blockIdx.x * blockDim.x + threadIdx.x;
    const float4* row = reinterpret_cast<const float4*>(emb + (size_t)i * Dm);
    double s = 0.0;
#pragma unroll
    for (int j = 0; j < Dm / 4; j++) {
        float4 e = row[j];
        s += (double)e.x * e.x + (double)e.y * e.y
           + (double)e.z * e.z + (double)e.w * e.w;
    }
    g_c2[i] = (float)s;
}

// ----------------- k_argmin: tiled screening + parallel fp64 rescue ---------
struct SmemT {
    unsigned long long z[32][PTS];    // 8KB : dim-pairs x points
    unsigned long long e[16][128];    // 16KB: dim-pairs (half-D) x codes
    float c2[KC];                     // 0.5KB
    union {
        struct { float best[16][PTS]; float best2[16][PTS]; int idx[16][PTS]; } m; // 6KB
        struct { double rb[256]; int ri[256]; } r;                                  // 3KB
    } u;
    int flag[PTS];
    int fidx[PTS];
};

__global__ void __launch_bounds__(256, 2)
k_argmin(const float* __restrict__ z, const float* __restrict__ emb,
         float* __restrict__ idx_out) {
    __shared__ SmemT s;
    const int tid = threadIdx.x;
    const int tx = tid & 15;          // point pair: pts 2tx, 2tx+1
    const int ty = tid >> 4;          // code group: codes ty*8 .. ty*8+7
    const int n0 = blockIdx.x * PTS;
    const int b  = n0 >> 12;
    const int t0 = n0 & (Tm - 1);
    const float* zb = z + ((size_t)b * Dm) * Tm + t0;
    const float4* emb4 = reinterpret_cast<const float4*>(emb);

    // ---- load z tile: 1024 u64, 4 per thread, coalesced along t ----
#pragma unroll
    for (int q = 0; q < 4; ++q) {
        int m  = tid + q * 256;
        int dp = m >> 5, pt = m & (PTS - 1);
        float x0 = zb[(size_t)(2 * dp) * Tm + pt];
        float x1 = zb[(size_t)(2 * dp + 1) * Tm + pt];
        s.z[dp][pt] = pack2(x0, x1);
    }

    unsigned long long acc[2][8];
#pragma unroll
    for (int i = 0; i < 2; ++i)
#pragma unroll
        for (int j = 0; j < 8; ++j) acc[i][j] = 0ull;

    float best[2], best2[2];
    int bidx[2];
#pragma unroll
    for (int i = 0; i < 2; ++i) { best[i] = 3.4e38f; best2[i] = 3.4e38f; bidx[i] = 0; }

    for (int kc = 0; kc < Km / KC; ++kc) {
#pragma unroll
        for (int half = 0; half < 2; ++half) {
            __syncthreads();
            // load e half-tile: codes kc*128.., dims half*32..+31 (packed pairs)
#pragma unroll
            for (int q = 0; q < 4; ++q) {
                int m = tid + q * 256;          // 0..1023
                int k = m >> 3, f = m & 7;
                float4 e4 = emb4[(size_t)(kc * KC + k) * (Dm / 4) + half * 8 + f];
                s.e[f * 2][k]     = pack2(e4.x, e4.y);
                s.e[f * 2 + 1][k] = pack2(e4.z, e4.w);
            }
            if (half == 0 && tid < KC) s.c2[tid] = g_c2[kc * KC + tid];
            __syncthreads();

            const int dbase = half * 16;
#pragma unroll 4
            for (int dp = 0; dp < 16; ++dp) {
                unsigned long long zr[2], er[8];
                ulonglong2 za = *reinterpret_cast<const ulonglong2*>(
                    &s.z[dbase + dp][2 * tx]);
                zr[0] = za.x; zr[1] = za.y;
                const ulonglong2* ep =
                    reinterpret_cast<const ulonglong2*>(&s.e[dp][ty * 8]);
#pragma unroll
                for (int jj = 0; jj < 4; ++jj) {
                    ulonglong2 ee = ep[jj];
                    er[2 * jj] = ee.x; er[2 * jj + 1] = ee.y;
                }
#pragma unroll
                for (int i = 0; i < 2; ++i)
#pragma unroll
                    for (int j = 0; j < 8; ++j) ffma2(acc[i][j], zr[i], er[j]);
            }
        }

        // ---- fold this chunk's dots into running best/best2 ----
#pragma unroll
        for (int i = 0; i < 2; ++i)
#pragma unroll
            for (int j = 0; j < 8; ++j) {
                float se, so;
                unpack2(acc[i][j], se, so);
                float dot  = se + so;
                float dist = fmaf(-2.0f, dot, s.c2[ty * 8 + j]);
                int   k    = kc * KC + ty * 8 + j;
                if (dist < best[i]) { best2[i] = best[i]; best[i] = dist; bidx[i] = k; }
                else if (dist < best2[i]) best2[i] = dist;
                acc[i][j] = 0ull;
            }
    }

    // ---- cross-thread merge per point ----
#pragma unroll
    for (int i = 0; i < 2; ++i) {
        int pt = 2 * tx + i;
        s.u.m.best[ty][pt]  = best[i];
        s.u.m.best2[ty][pt] = best2[i];
        s.u.m.idx[ty][pt]   = bidx[i];
    }
    __syncthreads();
    if (tid < PTS) {
        float b1 = 3.4e38f, b2 = 3.4e38f;
        int bi = 0;
        for (int t2 = 0; t2 < 16; ++t2) {     // ascending ty == ascending code idx
            float cb  = s.u.m.best[t2][tid];
            float cb2 = s.u.m.best2[t2][tid];
            int   ci  = s.u.m.idx[t2][tid];
            if (cb < b1) { b2 = fminf(b1, cb2); b1 = cb; bi = ci; }
            else b2 = fminf(b2, cb);
        }
        s.fidx[tid] = bi;
        s.flag[tid] = (b2 - b1 < TIE_MARGIN) ? 1 : 0;
    }
    __syncthreads();

    // ---- exact fp64 rescue for near-ties (block-parallel, rare) ----
    for (int pt = 0; pt < PTS; ++pt) {
        if (!s.flag[pt]) continue;            // uniform branch
        double bb = 1e300;
        int bi2 = 0;
#pragma unroll 1
        for (int q = 0; q < 4; ++q) {
            int k = tid * 4 + q;
            const float4* row = emb4 + (size_t)k * (Dm / 4);
            double ssum = 0.0;
#pragma unroll
            for (int jj = 0; jj < Dm / 4; ++jj) {
                float4 e = row[jj];
                float x0, x1, x2, x3;
                unpack2(s.z[2 * jj][pt], x0, x1);
                unpack2(s.z[2 * jj + 1][pt], x2, x3);
                double d0 = (double)x0 - e.x, d1 = (double)x1 - e.y;
                double d2 = (double)x2 - e.z, d3 = (double)x3 - e.w;
                ssum += d0 * d0 + d1 * d1 + d2 * d2 + d3 * d3;
            }
            if (ssum < bb) { bb = ssum; bi2 = k; }
        }
        s.u.r.rb[tid] = bb; s.u.r.ri[tid] = bi2;
        __syncthreads();
        for (int st = 128; st > 0; st >>= 1) {
            if (tid < st) {
                double o = s.u.r.rb[tid + st]; int oi = s.u.r.ri[tid + st];
                double m0 = s.u.r.rb[tid];     int mi = s.u.r.ri[tid];
                if (o < m0 || (o == m0 && oi < mi)) { s.u.r.rb[tid] = o; s.u.r.ri[tid] = oi; }
            }
            __syncthreads();
        }
        if (tid == 0) s.fidx[pt] = s.u.r.ri[0];
        __syncthreads();
    }

    // ---- per-point outputs + EMA segment sums ----
    if (tid < PTS) {
        int pt = tid, n = n0 + pt, idx = s.fidx[pt];
        g_indices[n] = idx;
        if (idx_out) idx_out[n] = (float)idx;
        atomicAdd(&g_counts[idx], 1.0f);
        float* dst = g_embed_sum + (size_t)idx * Dm;
#pragma unroll
        for (int j = 0; j < Dm / 4; ++j) {
            float x0, x1, x2, x3;
            unpack2(s.z[2 * j][pt], x0, x1);
            unpack2(s.z[2 * j + 1][pt], x2, x3);
            red_add_v4(dst + 4 * j, x0, x1, x2, x3);
        }
    }
}

// ----------------- k_cluster ------------------------------------------------
__global__ void k_cluster(const float* __restrict__ cluster_size) {
    __shared__ float red[Km];
    int k = threadIdx.x;
    float ncs = fmaf(cluster_size[k], DECAY, (1.0f - DECAY) * g_counts[k]);
    red[k] = ncs;
    __syncthreads();
    for (int s = Km / 2; s > 0; s >>= 1) {
        if (k < s) red[k] += red[k + s];
        __syncthreads();
    }
    float n = red[0];
    g_smoothed[k] = __fmul_rn(__fdiv_rn(ncs + EPSm, n + (float)Km * EPSm), n);
}

// ----------------- k_embed --------------------------------------------------
__global__ void k_embed(const float* __restrict__ embed_avg) {
    int i = blockIdx.x * blockDim.x + threadIdx.x;
    float na = fmaf(embed_avg[i], DECAY, (1.0f - DECAY) * g_embed_sum[i]);
    g_new_embedding[i] = __fdiv_rn(na, g_smoothed[i >> 6]);
}

// ----------------- k_quant --------------------------------------------------
__global__ void __launch_bounds__(256)
k_quant(const float* __restrict__ z, float* __restrict__ out) {
    __shared__ float red[256];
    const int n = blockIdx.x * 256 + threadIdx.x;
    const int b = n >> 12;
    const int t = n & (Tm - 1);
    const float* zb = z + ((size_t)b * Dm) * Tm + t;
    float* ob = out + OFF_ZQ + ((size_t)b * Dm) * Tm + t;

    const int idx = g_indices[n];
    const float4* row = reinterpret_cast<const float4*>(g_new_embedding + (size_t)idx * Dm);

    float acc = 0.0f;
#pragma unroll
    for (int j = 0; j < Dm / 4; j++) {
        float4 e = row[j];
        float zv, df;
        zv = zb[(size_t)(4 * j + 0) * Tm]; ob[(size_t)(4 * j + 0) * Tm] = e.x; df = zv - e.x; acc = fmaf(df, df, acc);
        zv = zb[(size_t)(4 * j + 1) * Tm]; ob[(size_t)(4 * j + 1) * Tm] = e.y; df = zv - e.y; acc = fmaf(df, df, acc);
        zv = zb[(size_t)(4 * j + 2) * Tm]; ob[(size_t)(4 * j + 2) * Tm] = e.z; df = zv - e.z; acc = fmaf(df, df, acc);
        zv = zb[(size_t)(4 * j + 3) * Tm]; ob[(size_t)(4 * j + 3) * Tm] = e.w; df = zv - e.w; acc = fmaf(df, df, acc);
    }

    red[threadIdx.x] = acc;
    __syncthreads();
    for (int st = 128; st > 0; st >>= 1) {
        if (threadIdx.x < st) red[threadIdx.x] += red[threadIdx.x + st];
        __syncthreads();
    }
    if (threadIdx.x == 0) atomicAdd(&g_loss, red[0]);
}

// ----------------- k_final --------------------------------------------------
__global__ void k_final(float* __restrict__ loss_out) {
    loss_out[0] = 0.25f * __fdiv_rn(g_loss, (float)((size_t)Nm * Dm));
}

// ----------------- launch ----------------------------------------------------
extern "C" void kernel_launch(void* const* d_in, const int* in_sizes, int n_in,
                              void* d_out, int out_size) {
    const float* z    = (const float*)d_in[0];
    const float* emb  = (const float*)d_in[1];
    const float* cs   = (const float*)d_in[2];
    const float* avg  = (const float*)d_in[3];
    float* out = (float*)d_out;

    const bool full = ((size_t)out_size >= SZ_FULL);
    float* idx_out  = full ? out + OFF_IDX  : nullptr;
    float* loss_out = full ? out + OFF_LOSS : nullptr;

    k_zero1<<<Km * Dm / 2 / 1024, 1024>>>();
    k_zero2<<<(Km * Dm / 2 + Km + 1 + 1023) / 1024, 1024>>>();
    k_c2<<<Km / 256, 256>>>(emb);
    k_argmin<<<Nm / PTS, 256>>>(z, emb, idx_out);      // launch index 3
    k_cluster<<<1, Km>>>(cs);
    k_embed<<<(Km * Dm) / 1024, 1024>>>(avg);
    k_quant<<<Nm / 256, 256>>>(z, out);
    if (loss_out) k_final<<<1, 1>>>(loss_out);
}

// round 11
// speedup vs baseline: 11.1628x; 1.0271x over previous
#include <cuda_runtime.h>
#include <cuda_bf16.h>
#include <cstdint>

// ---------------------------------------------------------------------------
// VectorQuantizerEMA on GB300 (sm_103a) — R11
// mma.sync (HMMA bf16, baseline PTX -> legal on compute_103 target) screening:
//   augmented K=208: [zhi|zlo|zhi|1,1,1|0...] x [ehi|ehi|elo|-c2/2 splits|0...]
//   => D' = dot_fp32ish - 0.5*||e||^2 ; argmin dist == argmax D'
// + exact fp64 tie rescue (unchanged semantics), EMA via vector REDG.
// ---------------------------------------------------------------------------

namespace {
constexpr int Dm   = 64;
constexpr int Tm   = 4096;
constexpr int Bm   = 32;
constexpr int Km   = 1024;
constexpr int Nm   = Bm * Tm;      // 131072
constexpr int MPTS = 128;          // points per block
constexpr int NCH  = 128;          // codes per chunk
constexpr int NCHUNK = Km / NCH;   // 8
constexpr int KAUG = 208;          // 64*3 + 16 (3 c2 slots + 13 zero)
constexpr int KSTEPS = KAUG / 16;  // 13
constexpr int ROWB = KAUG + 8;     // 216 bf16 = 432B row stride (bank-safe)
constexpr float DECAY = 0.99f;
constexpr float EPSm  = 1e-5f;
constexpr float MARGIN_D = 7.5e-3f;   // on D' (dist gap = 2x this = 1.5e-2)

constexpr size_t OFF_ZQ   = 0;
constexpr size_t SZ_ZQ    = (size_t)Bm * Dm * Tm;
constexpr size_t OFF_LOSS = SZ_ZQ;
constexpr size_t OFF_IDX  = SZ_ZQ + 1;
constexpr size_t SZ_FULL  = SZ_ZQ + 1 + (size_t)Nm;

// dynamic smem layout (bytes)
constexpr int S_FLAG = 0;         // 128*4
constexpr int S_FIDX = 512;       // 128*4
constexpr int S_RB   = 1024;      // 256*8
constexpr int S_RI   = 3072;      // 256*4
constexpr int S_BM   = 4096;      // 2*128*4
constexpr int S_B2M  = 5120;      // 2*128*4
constexpr int S_IM   = 6144;      // 2*128*4
constexpr int S_Z32  = 7168;      // 128*65*4 = 33280
constexpr int S_A    = 40448;     // 128*432  = 55296
constexpr int S_B    = 95744;     // 128*432  = 55296
constexpr int SMEM_SZ= 151040;
}

// ----------------- device scratch ------------------------------------------
__device__ float g_counts[Km];
__device__ __align__(16) float g_embed_sum[Km * Dm];
__device__ float g_smoothed[Km];
__device__ __align__(16) float g_new_embedding[Km * Dm];
__device__ int   g_indices[Nm];
__device__ float g_loss;
__device__ __align__(16) __nv_bfloat16 g_beq[Km * ROWB];   // augmented B rows

// ----------------- helpers --------------------------------------------------
__device__ __forceinline__ uint32_t smem_u32(const void* p) {
    uint32_t a;
    asm("{ .reg .u64 t; cvta.to.shared.u64 t, %1; cvt.u32.u64 %0, t; }"
        : "=r"(a) : "l"(p));
    return a;
}
__device__ __forceinline__ void red_add_v4(float* p, float a, float b, float c, float d) {
    asm volatile("red.global.add.v4.f32 [%0], {%1, %2, %3, %4};"
                 :: "l"(p), "f"(a), "f"(b), "f"(c), "f"(d) : "memory");
}
__device__ __forceinline__ void ldsm_x4(uint32_t& r0, uint32_t& r1,
                                        uint32_t& r2, uint32_t& r3, uint32_t addr) {
    asm volatile("ldmatrix.sync.aligned.m8n8.x4.shared.b16 {%0,%1,%2,%3}, [%4];"
                 : "=r"(r0), "=r"(r1), "=r"(r2), "=r"(r3) : "r"(addr));
}
__device__ __forceinline__ void mma16816(float* d, const uint32_t* a,
                                         const uint32_t* b) {
    asm volatile(
        "mma.sync.aligned.m16n8k16.row.col.f32.bf16.bf16.f32 "
        "{%0,%1,%2,%3}, {%4,%5,%6,%7}, {%8,%9}, {%0,%1,%2,%3};"
        : "+f"(d[0]), "+f"(d[1]), "+f"(d[2]), "+f"(d[3])
        : "r"(a[0]), "r"(a[1]), "r"(a[2]), "r"(a[3]), "r"(b[0]), "r"(b[1]));
}

// ----------------- init kernels ----------------------------------------------
__global__ void k_zero1() {
    int i = blockIdx.x * blockDim.x + threadIdx.x;
    g_embed_sum[i] = 0.0f;
}
__global__ void k_zero2() {
    int i = blockIdx.x * blockDim.x + threadIdx.x;
    if (i < Km * Dm / 2) g_embed_sum[Km * Dm / 2 + i] = 0.0f;
    else if (i < Km * Dm / 2 + Km) g_counts[i - Km * Dm / 2] = 0.0f;
    else if (i == Km * Dm / 2 + Km) g_loss = 0.0f;
}
// build augmented B rows: [ehi|ehi|elo| -c2/2 hi,lo,ll | zeros]
__global__ void k_prep(const float* __restrict__ emb) {
    int k = blockIdx.x * blockDim.x + threadIdx.x;     // 1024
    const float* row = emb + (size_t)k * Dm;
    __nv_bfloat16* dst = g_beq + (size_t)k * ROWB;
    double s = 0.0;
#pragma unroll
    for (int d = 0; d < Dm; ++d) {
        float f = row[d];
        s += (double)f * f;
        __nv_bfloat16 hi = __float2bfloat16_rn(f);
        float rem = f - __bfloat162float(hi);
        __nv_bfloat16 lo = __float2bfloat16_rn(rem);
        dst[d] = hi;
        dst[64 + d] = hi;
        dst[128 + d] = lo;
    }
    double c = -0.5 * s;
    float c1 = (float)c;
    __nv_bfloat16 h0 = __float2bfloat16_rn(c1);
    float r1 = (float)(c - (double)__bfloat162float(h0));
    __nv_bfloat16 h1 = __float2bfloat16_rn(r1);
    float r2 = r1 - __bfloat162float(h1);
    __nv_bfloat16 h2 = __float2bfloat16_rn(r2);
    dst[192] = h0; dst[193] = h1; dst[194] = h2;
#pragma unroll
    for (int j = 195; j < ROWB; ++j) dst[j] = __float2bfloat16_rn(0.0f);
}

// ----------------- k_argmin: HMMA screening + fp64 rescue --------------------
__global__ void __launch_bounds__(256, 1)
k_argmin(const float* __restrict__ z, const float* __restrict__ emb,
         float* __restrict__ idx_out) {
    extern __shared__ char smem[];
    const uint32_t sbase = smem_u32(smem);
    float*  z32   = reinterpret_cast<float*>(smem + S_Z32);     // [128][65]
    int*    s_flag = reinterpret_cast<int*>(smem + S_FLAG);
    int*    s_fidx = reinterpret_cast<int*>(smem + S_FIDX);
    double* s_rb   = reinterpret_cast<double*>(smem + S_RB);
    int*    s_ri   = reinterpret_cast<int*>(smem + S_RI);
    float*  s_bm   = reinterpret_cast<float*>(smem + S_BM);     // [2][128]
    float*  s_b2m  = reinterpret_cast<float*>(smem + S_B2M);
    int*    s_im   = reinterpret_cast<int*>(smem + S_IM);

    const int tid  = threadIdx.x;
    const int wid  = tid >> 5;
    const int lane = tid & 31;
    const int wm   = wid >> 1;        // 0..3 : point rows wm*32..
    const int wn   = wid & 1;         // 0..1 : code cols wn*64..
    const int n0   = blockIdx.x * MPTS;
    const int b    = n0 >> 12;
    const int t0   = n0 & (Tm - 1);
    const float* zb = z + ((size_t)b * Dm) * Tm + t0;

    // ---- load z tile (coalesced along t) ----
#pragma unroll
    for (int q = 0; q < 32; ++q) {
        int m = tid + q * 256;            // 8192
        int d = m >> 7, t = m & 127;
        z32[t * 65 + d] = zb[(size_t)d * Tm + t];
    }
    __syncthreads();

    // ---- build augmented A rows in smem (bf16, stride 216) ----
    {
        int pt = tid & 127, h = tid >> 7;             // h = dim half
        __nv_bfloat16* arow = reinterpret_cast<__nv_bfloat16*>(smem + S_A) +
                              (size_t)pt * ROWB;
#pragma unroll
        for (int dd = 0; dd < 32; ++dd) {
            int d = h * 32 + dd;
            float f = z32[pt * 65 + d];
            __nv_bfloat16 hi = __float2bfloat16_rn(f);
            __nv_bfloat16 lo = __float2bfloat16_rn(f - __bfloat162float(hi));
            arow[d] = hi;
            arow[64 + d] = lo;
            arow[128 + d] = hi;
        }
        if (h == 1) {
            const __nv_bfloat16 one = __float2bfloat16_rn(1.0f);
            const __nv_bfloat16 zero = __float2bfloat16_rn(0.0f);
#pragma unroll
            for (int j = 192; j < ROWB; ++j) arow[j] = (j < 195) ? one : zero;
        }
    }

    // ---- per-lane ldmatrix base addresses ----
    const int sel = lane >> 3, l8 = lane & 7;
    // A x4: lanes 0-7 rows+0 k0 | 8-15 rows+8 k0 | 16-23 rows+0 k+8 | 24-31 rows+8 k+8
    const uint32_t aBase = sbase + S_A +
        (uint32_t)((wm * 32 + l8 + (sel & 1) * 8) * 432 + ((sel >> 1) & 1) * 16);
    // B x4: lanes 0-7 n+0 k0 | 8-15 n+0 k+8 | 16-23 n+8 k0 | 24-31 n+8 k+8
    const uint32_t bBase = sbase + S_B +
        (uint32_t)((wn * 64 + l8 + ((sel >> 1) & 1) * 8) * 432 + (sel & 1) * 16);

    float dacc[2][8][4];
    float bestv[4], best2v[4];
    int   bidx[4];
#pragma unroll
    for (int s = 0; s < 4; ++s) { bestv[s] = -3.4e38f; best2v[s] = -3.4e38f; bidx[s] = 0; }

    const uint4* beq4 = reinterpret_cast<const uint4*>(g_beq);

    for (int ch = 0; ch < NCHUNK; ++ch) {
        const int cb = ch * NCH;
        __syncthreads();                  // prior reads of B done
        // ---- copy B chunk: 128 rows x 27 uint4 ----
        for (int m = tid; m < 128 * 27; m += 256) {
            int row = m / 27, u = m - row * 27;
            *reinterpret_cast<uint4*>(smem + S_B + row * 432 + u * 16) =
                beq4[(size_t)(cb + row) * 27 + u];
        }
        __syncthreads();

#pragma unroll
        for (int mt = 0; mt < 2; ++mt)
#pragma unroll
            for (int nt = 0; nt < 8; ++nt)
#pragma unroll
                for (int c = 0; c < 4; ++c) dacc[mt][nt][c] = 0.0f;

        uint32_t aAddr = aBase, bAddr = bBase;
#pragma unroll 1
        for (int ks = 0; ks < KSTEPS; ++ks) {
            uint32_t a0[4], a1[4], bb[16];
            ldsm_x4(a0[0], a0[1], a0[2], a0[3], aAddr);
            ldsm_x4(a1[0], a1[1], a1[2], a1[3], aAddr + 16 * 432);
#pragma unroll
            for (int np = 0; np < 4; ++np)
                ldsm_x4(bb[4 * np], bb[4 * np + 1], bb[4 * np + 2], bb[4 * np + 3],
                        bAddr + np * 16 * 432);
#pragma unroll
            for (int nt = 0; nt < 8; ++nt) {
                const uint32_t* bp = &bb[(nt >> 1) * 4 + (nt & 1) * 2];
                mma16816(dacc[0][nt], a0, bp);
                mma16816(dacc[1][nt], a1, bp);
            }
            aAddr += 32;
            bAddr += 32;
        }

        // ---- fold into per-point running max/max2 ----
#pragma unroll
        for (int mt = 0; mt < 2; ++mt)
#pragma unroll
            for (int nt = 0; nt < 8; ++nt) {
                int k0 = cb + wn * 64 + nt * 8 + 2 * (lane & 3);
#pragma unroll
                for (int c = 0; c < 4; ++c) {
                    int s = mt * 2 + (c >> 1);
                    float v = dacc[mt][nt][c];
                    int   k = k0 + (c & 1);
                    if (v > bestv[s]) { best2v[s] = bestv[s]; bestv[s] = v; bidx[s] = k; }
                    else if (v > best2v[s]) best2v[s] = v;
                }
            }
    }

    // ---- warp merge across the 4 lanes sharing each point (lane&3) ----
#pragma unroll
    for (int st = 1; st <= 2; st <<= 1) {
#pragma unroll
        for (int s = 0; s < 4; ++s) {
            float ob  = __shfl_xor_sync(0xFFFFFFFFu, bestv[s],  st);
            float ob2 = __shfl_xor_sync(0xFFFFFFFFu, best2v[s], st);
            int   oi  = __shfl_xor_sync(0xFFFFFFFFu, bidx[s],   st);
            if (ob > bestv[s]) {
                best2v[s] = fmaxf(bestv[s], ob2);
                bestv[s] = ob; bidx[s] = oi;
            } else {
                best2v[s] = fmaxf(best2v[s], ob);
            }
        }
    }
    if ((lane & 3) == 0) {
#pragma unroll
        for (int s = 0; s < 4; ++s) {
            int pt = wm * 32 + (lane >> 2) + s * 8;
            s_bm[wn * 128 + pt]  = bestv[s];
            s_b2m[wn * 128 + pt] = best2v[s];
            s_im[wn * 128 + pt]  = bidx[s];
        }
    }
    __syncthreads();

    // ---- final merge across the 2 warp columns, flag near-ties ----
    if (tid < MPTS) {
        float m0 = s_bm[tid],        m1 = s_bm[128 + tid];
        float q0 = s_b2m[tid],       q1 = s_b2m[128 + tid];
        int   i0 = s_im[tid],        i1 = s_im[128 + tid];
        float mx, m2; int ix;
        if (m0 >= m1) { mx = m0; ix = i0; m2 = fmaxf(q0, m1); }
        else          { mx = m1; ix = i1; m2 = fmaxf(q1, m0); }
        s_fidx[tid] = ix;
        s_flag[tid] = (mx - m2 < MARGIN_D) ? 1 : 0;
    }
    __syncthreads();

    // ---- exact fp64 rescue for near-ties (block-parallel, rare) ----
    const float4* emb4 = reinterpret_cast<const float4*>(emb);
#pragma unroll 1
    for (int pt = 0; pt < MPTS; ++pt) {
        if (!s_flag[pt]) continue;        // uniform
        double bb = 1e300;
        int bi2 = 0;
#pragma unroll 1
        for (int q = 0; q < 4; ++q) {
            int k = tid * 4 + q;
            const float4* row = emb4 + (size_t)k * (Dm / 4);
            double ssum = 0.0;
#pragma unroll
            for (int jj = 0; jj < Dm / 4; ++jj) {
                float4 e = row[jj];
                double d0 = (double)z32[pt * 65 + 4 * jj]     - e.x;
                double d1 = (double)z32[pt * 65 + 4 * jj + 1] - e.y;
                double d2 = (double)z32[pt * 65 + 4 * jj + 2] - e.z;
                double d3 = (double)z32[pt * 65 + 4 * jj + 3] - e.w;
                ssum += d0 * d0 + d1 * d1 + d2 * d2 + d3 * d3;
            }
            if (ssum < bb) { bb = ssum; bi2 = k; }
        }
        s_rb[tid] = bb; s_ri[tid] = bi2;
        __syncthreads();
        for (int st = 128; st > 0; st >>= 1) {
            if (tid < st) {
                double o = s_rb[tid + st]; int oi = s_ri[tid + st];
                double m0 = s_rb[tid];     int mi = s_ri[tid];
                if (o < m0 || (o == m0 && oi < mi)) { s_rb[tid] = o; s_ri[tid] = oi; }
            }
            __syncthreads();
        }
        if (tid == 0) s_fidx[pt] = s_ri[0];
        __syncthreads();
    }
    __syncthreads();

    // ---- per-point outputs + EMA segment sums ----
    if (tid < MPTS) {
        int pt = tid, n = n0 + pt, idx = s_fidx[pt];
        g_indices[n] = idx;
        if (idx_out) idx_out[n] = (float)idx;
        atomicAdd(&g_counts[idx], 1.0f);
        float* dst = g_embed_sum + (size_t)idx * Dm;
#pragma unroll
        for (int j = 0; j < Dm / 4; ++j)
            red_add_v4(dst + 4 * j,
                       z32[pt * 65 + 4 * j],     z32[pt * 65 + 4 * j + 1],
                       z32[pt * 65 + 4 * j + 2], z32[pt * 65 + 4 * j + 3]);
    }
}

// ----------------- k_cluster ------------------------------------------------
__global__ void k_cluster(const float* __restrict__ cluster_size) {
    __shared__ float red[Km];
    int k = threadIdx.x;
    float ncs = fmaf(cluster_size[k], DECAY, (1.0f - DECAY) * g_counts[k]);
    red[k] = ncs;
    __syncthreads();
    for (int s = Km / 2; s > 0; s >>= 1) {
        if (k < s) red[k] += red[k + s];
        __syncthreads();
    }
    float n = red[0];
    g_smoothed[k] = __fmul_rn(__fdiv_rn(ncs + EPSm, n + (float)Km * EPSm), n);
}

// ----------------- k_embed --------------------------------------------------
__global__ void k_embed(const float* __restrict__ embed_avg) {
    int i = blockIdx.x * blockDim.x + threadIdx.x;
    float na = fmaf(embed_avg[i], DECAY, (1.0f - DECAY) * g_embed_sum[i]);
    g_new_embedding[i] = __fdiv_rn(na, g_smoothed[i >> 6]);
}

// ----------------- k_quant --------------------------------------------------
__global__ void __launch_bounds__(256)
k_quant(const float* __restrict__ z, float* __restrict__ out) {
    __shared__ float red[256];
    const int n = blockIdx.x * 256 + threadIdx.x;
    const int b = n >> 12;
    const int t = n & (Tm - 1);
    const float* zb = z + ((size_t)b * Dm) * Tm + t;
    float* ob = out + OFF_ZQ + ((size_t)b * Dm) * Tm + t;

    const int idx = g_indices[n];
    const float4* row = reinterpret_cast<const float4*>(g_new_embedding + (size_t)idx * Dm);

    float acc = 0.0f;
#pragma unroll
    for (int j = 0; j < Dm / 4; j++) {
        float4 e = row[j];
        float zv, df;
        zv = zb[(size_t)(4 * j + 0) * Tm]; ob[(size_t)(4 * j + 0) * Tm] = e.x; df = zv - e.x; acc = fmaf(df, df, acc);
        zv = zb[(size_t)(4 * j + 1) * Tm]; ob[(size_t)(4 * j + 1) * Tm] = e.y; df = zv - e.y; acc = fmaf(df, df, acc);
        zv = zb[(size_t)(4 * j + 2) * Tm]; ob[(size_t)(4 * j + 2) * Tm] = e.z; df = zv - e.z; acc = fmaf(df, df, acc);
        zv = zb[(size_t)(4 * j + 3) * Tm]; ob[(size_t)(4 * j + 3) * Tm] = e.w; df = zv - e.w; acc = fmaf(df, df, acc);
    }

    red[threadIdx.x] = acc;
    __syncthreads();
    for (int st = 128; st > 0; st >>= 1) {
        if (threadIdx.x < st) red[threadIdx.x] += red[threadIdx.x + st];
        __syncthreads();
    }
    if (threadIdx.x == 0) atomicAdd(&g_loss, red[0]);
}

// ----------------- k_final --------------------------------------------------
__global__ void k_final(float* __restrict__ loss_out) {
    loss_out[0] = 0.25f * __fdiv_rn(g_loss, (float)((size_t)Nm * Dm));
}

// ----------------- launch ----------------------------------------------------
extern "C" void kernel_launch(void* const* d_in, const int* in_sizes, int n_in,
                              void* d_out, int out_size) {
    const float* z    = (const float*)d_in[0];
    const float* emb  = (const float*)d_in[1];
    const float* cs   = (const float*)d_in[2];
    const float* avg  = (const float*)d_in[3];
    float* out = (float*)d_out;

    const bool full = ((size_t)out_size >= SZ_FULL);
    float* idx_out  = full ? out + OFF_IDX  : nullptr;
    float* loss_out = full ? out + OFF_LOSS : nullptr;

    cudaFuncSetAttribute(k_argmin, cudaFuncAttributeMaxDynamicSharedMemorySize, SMEM_SZ);

    k_zero1<<<Km * Dm / 2 / 1024, 1024>>>();
    k_zero2<<<(Km * Dm / 2 + Km + 1 + 1023) / 1024, 1024>>>();
    k_prep<<<Km / 256, 256>>>(emb);
    k_argmin<<<Nm / MPTS, 256, SMEM_SZ>>>(z, emb, idx_out);
    k_cluster<<<1, Km>>>(cs);
    k_embed<<<(Km * Dm) / 1024, 1024>>>(avg);
    k_quant<<<Nm / 256, 256>>>(z, out);
    if (loss_out) k_final<<<1, 1>>>(loss_out);
}

// round 12
// speedup vs baseline: 11.5180x; 1.0318x over previous
#include <cuda_runtime.h>
#include <cuda_bf16.h>
#include <cstdint>

// ---------------------------------------------------------------------------
// VectorQuantizerEMA on GB300 (sm_103a) — R12
// R11 HMMA screening + two-level pipelining:
//   - frag-level: double-buffered ldmatrix, next kstep prefetched before MMAs
//   - chunk-level: cp.async double-buffered B tiles (copy overlaps compute)
// Math identical to R11 (augmented K=208 bf16 split, D' = dot - c2/2,
// exact fp64 tie rescue).
// ---------------------------------------------------------------------------

namespace {
constexpr int Dm   = 64;
constexpr int Tm   = 4096;
constexpr int Bm   = 32;
constexpr int Km   = 1024;
constexpr int Nm   = Bm * Tm;      // 131072
constexpr int MPTS = 128;          // points per block
constexpr int NCH  = 128;          // codes per chunk
constexpr int NCHUNK = Km / NCH;   // 8
constexpr int KAUG = 208;
constexpr int KSTEPS = KAUG / 16;  // 13
constexpr int ROWB = KAUG + 8;     // 216 bf16 = 432B row stride
constexpr float DECAY = 0.99f;
constexpr float EPSm  = 1e-5f;
constexpr float MARGIN_D = 7.5e-3f;

constexpr size_t OFF_ZQ   = 0;
constexpr size_t SZ_ZQ    = (size_t)Bm * Dm * Tm;
constexpr size_t OFF_LOSS = SZ_ZQ;
constexpr size_t OFF_IDX  = SZ_ZQ + 1;
constexpr size_t SZ_FULL  = SZ_ZQ + 1 + (size_t)Nm;

// dynamic smem layout (bytes)
constexpr int S_FLAG = 0;         // 128*4
constexpr int S_FIDX = 512;
constexpr int S_RB   = 1024;      // 256*8
constexpr int S_RI   = 3072;
constexpr int S_BM   = 4096;      // 2*128*4
constexpr int S_B2M  = 5120;
constexpr int S_IM   = 6144;
constexpr int S_Z32  = 7168;      // 128*65*4 = 33280
constexpr int S_A    = 40448;     // 128*432 = 55296
constexpr int S_B0   = 95744;     // 55296
constexpr int S_B1   = 151040;    // 55296
constexpr int SMEM_SZ= 206336;    // < 227KB cap
}

// ----------------- device scratch ------------------------------------------
__device__ float g_counts[Km];
__device__ __align__(16) float g_embed_sum[Km * Dm];
__device__ float g_smoothed[Km];
__device__ __align__(16) float g_new_embedding[Km * Dm];
__device__ int   g_indices[Nm];
__device__ float g_loss;
__device__ __align__(16) __nv_bfloat16 g_beq[Km * ROWB];   // augmented B rows

// ----------------- helpers --------------------------------------------------
__device__ __forceinline__ uint32_t smem_u32(const void* p) {
    uint32_t a;
    asm("{ .reg .u64 t; cvta.to.shared.u64 t, %1; cvt.u32.u64 %0, t; }"
        : "=r"(a) : "l"(p));
    return a;
}
__device__ __forceinline__ void red_add_v4(float* p, float a, float b, float c, float d) {
    asm volatile("red.global.add.v4.f32 [%0], {%1, %2, %3, %4};"
                 :: "l"(p), "f"(a), "f"(b), "f"(c), "f"(d) : "memory");
}
__device__ __forceinline__ void ldsm_x4(uint32_t& r0, uint32_t& r1,
                                        uint32_t& r2, uint32_t& r3, uint32_t addr) {
    asm volatile("ldmatrix.sync.aligned.m8n8.x4.shared.b16 {%0,%1,%2,%3}, [%4];"
                 : "=r"(r0), "=r"(r1), "=r"(r2), "=r"(r3) : "r"(addr));
}
__device__ __forceinline__ void mma16816(float* d, const uint32_t* a,
                                         const uint32_t* b) {
    asm volatile(
        "mma.sync.aligned.m16n8k16.row.col.f32.bf16.bf16.f32 "
        "{%0,%1,%2,%3}, {%4,%5,%6,%7}, {%8,%9}, {%0,%1,%2,%3};"
        : "+f"(d[0]), "+f"(d[1]), "+f"(d[2]), "+f"(d[3])
        : "r"(a[0]), "r"(a[1]), "r"(a[2]), "r"(a[3]), "r"(b[0]), "r"(b[1]));
}
__device__ __forceinline__ void cp_async16(uint32_t saddr, const void* gptr) {
    asm volatile("cp.async.cg.shared.global [%0], [%1], 16;"
                 :: "r"(saddr), "l"(gptr) : "memory");
}
#define CP_COMMIT() asm volatile("cp.async.commit_group;" ::: "memory")
#define CP_WAIT0()  asm volatile("cp.async.wait_group 0;" ::: "memory")

// ----------------- init kernels ----------------------------------------------
__global__ void k_zero1() {
    int i = blockIdx.x * blockDim.x + threadIdx.x;
    g_embed_sum[i] = 0.0f;
}
__global__ void k_zero2() {
    int i = blockIdx.x * blockDim.x + threadIdx.x;
    if (i < Km * Dm / 2) g_embed_sum[Km * Dm / 2 + i] = 0.0f;
    else if (i < Km * Dm / 2 + Km) g_counts[i - Km * Dm / 2] = 0.0f;
    else if (i == Km * Dm / 2 + Km) g_loss = 0.0f;
}
// build augmented B rows: [ehi|ehi|elo| -c2/2 hi,lo,ll | zeros]
__global__ void k_prep(const float* __restrict__ emb) {
    int k = blockIdx.x * blockDim.x + threadIdx.x;     // 1024
    const float* row = emb + (size_t)k * Dm;
    __nv_bfloat16* dst = g_beq + (size_t)k * ROWB;
    double s = 0.0;
#pragma unroll
    for (int d = 0; d < Dm; ++d) {
        float f = row[d];
        s += (double)f * f;
        __nv_bfloat16 hi = __float2bfloat16_rn(f);
        float rem = f - __bfloat162float(hi);
        __nv_bfloat16 lo = __float2bfloat16_rn(rem);
        dst[d] = hi;
        dst[64 + d] = hi;
        dst[128 + d] = lo;
    }
    double c = -0.5 * s;
    float c1 = (float)c;
    __nv_bfloat16 h0 = __float2bfloat16_rn(c1);
    float r1 = (float)(c - (double)__bfloat162float(h0));
    __nv_bfloat16 h1 = __float2bfloat16_rn(r1);
    float r2 = r1 - __bfloat162float(h1);
    __nv_bfloat16 h2 = __float2bfloat16_rn(r2);
    dst[192] = h0; dst[193] = h1; dst[194] = h2;
#pragma unroll
    for (int j = 195; j < ROWB; ++j) dst[j] = __float2bfloat16_rn(0.0f);
}

// ----------------- k_argmin: pipelined HMMA screening + fp64 rescue ----------
__global__ void __launch_bounds__(256, 1)
k_argmin(const float* __restrict__ z, const float* __restrict__ emb,
         float* __restrict__ idx_out) {
    extern __shared__ char smem[];
    const uint32_t sbase = smem_u32(smem);
    float*  z32    = reinterpret_cast<float*>(smem + S_Z32);     // [128][65]
    int*    s_flag = reinterpret_cast<int*>(smem + S_FLAG);
    int*    s_fidx = reinterpret_cast<int*>(smem + S_FIDX);
    double* s_rb   = reinterpret_cast<double*>(smem + S_RB);
    int*    s_ri   = reinterpret_cast<int*>(smem + S_RI);
    float*  s_bm   = reinterpret_cast<float*>(smem + S_BM);      // [2][128]
    float*  s_b2m  = reinterpret_cast<float*>(smem + S_B2M);
    int*    s_im   = reinterpret_cast<int*>(smem + S_IM);

    const int tid  = threadIdx.x;
    const int wid  = tid >> 5;
    const int lane = tid & 31;
    const int wm   = wid >> 1;        // 0..3
    const int wn   = wid & 1;         // 0..1
    const int n0   = blockIdx.x * MPTS;
    const int b    = n0 >> 12;
    const int t0   = n0 & (Tm - 1);
    const float* zb = z + ((size_t)b * Dm) * Tm + t0;
    const uint4* beq4 = reinterpret_cast<const uint4*>(g_beq);

    // ---- kick off async copy of B chunk 0 first (overlaps A build) ----
    for (int m = tid; m < 128 * 27; m += 256) {
        int row = m / 27, u = m - row * 27;
        cp_async16(sbase + S_B0 + row * 432 + u * 16,
                   &beq4[(size_t)row * 27 + u]);
    }
    CP_COMMIT();

    // ---- load z tile (coalesced along t) ----
#pragma unroll
    for (int q = 0; q < 32; ++q) {
        int m = tid + q * 256;
        int d = m >> 7, t = m & 127;
        z32[t * 65 + d] = zb[(size_t)d * Tm + t];
    }
    __syncthreads();

    // ---- build augmented A rows (bf16, stride 216) ----
    {
        int pt = tid & 127, h = tid >> 7;
        __nv_bfloat16* arow = reinterpret_cast<__nv_bfloat16*>(smem + S_A) +
                              (size_t)pt * ROWB;
#pragma unroll
        for (int dd = 0; dd < 32; ++dd) {
            int d = h * 32 + dd;
            float f = z32[pt * 65 + d];
            __nv_bfloat16 hi = __float2bfloat16_rn(f);
            __nv_bfloat16 lo = __float2bfloat16_rn(f - __bfloat162float(hi));
            arow[d] = hi;
            arow[64 + d] = lo;
            arow[128 + d] = hi;
        }
        if (h == 1) {
            const __nv_bfloat16 one  = __float2bfloat16_rn(1.0f);
            const __nv_bfloat16 zero = __float2bfloat16_rn(0.0f);
#pragma unroll
            for (int j = 192; j < ROWB; ++j) arow[j] = (j < 195) ? one : zero;
        }
    }

    // ---- per-lane ldmatrix base addresses ----
    const int sel = lane >> 3, l8 = lane & 7;
    const uint32_t aBase = sbase + S_A +
        (uint32_t)((wm * 32 + l8 + (sel & 1) * 8) * 432 + ((sel >> 1) & 1) * 16);
    const uint32_t bOff =
        (uint32_t)((wn * 64 + l8 + ((sel >> 1) & 1) * 8) * 432 + (sel & 1) * 16);
    const uint32_t bBasePing = sbase + S_B0 + bOff;
    const uint32_t bBasePong = sbase + S_B1 + bOff;

    float dacc[2][8][4];
    float bestv[4], best2v[4];
    int   bidx[4];
#pragma unroll
    for (int s = 0; s < 4; ++s) { bestv[s] = -3.4e38f; best2v[s] = -3.4e38f; bidx[s] = 0; }

    CP_WAIT0();
    __syncthreads();                       // B chunk 0 resident

    for (int ch = 0; ch < NCHUNK; ++ch) {
        const int cb = ch * NCH;
        const uint32_t bBase = (ch & 1) ? bBasePong : bBasePing;

        // prefetch next chunk into the other buffer (overlaps MMA below)
        if (ch + 1 < NCHUNK) {
            const uint32_t dstB = sbase + ((ch & 1) ? S_B0 : S_B1);
            for (int m = tid; m < 128 * 27; m += 256) {
                int row = m / 27, u = m - row * 27;
                cp_async16(dstB + row * 432 + u * 16,
                           &beq4[(size_t)((ch + 1) * NCH + row) * 27 + u]);
            }
            CP_COMMIT();
        }

#pragma unroll
        for (int mt = 0; mt < 2; ++mt)
#pragma unroll
            for (int nt = 0; nt < 8; ++nt)
#pragma unroll
                for (int c = 0; c < 4; ++c) dacc[mt][nt][c] = 0.0f;

        // ---- software-pipelined kstep loop (double-buffered frags) ----
        uint32_t afr[2][8], bfr[2][16];
        {   // prologue: frags for ks=0 into set 0
            ldsm_x4(afr[0][0], afr[0][1], afr[0][2], afr[0][3], aBase);
            ldsm_x4(afr[0][4], afr[0][5], afr[0][6], afr[0][7], aBase + 16 * 432);
#pragma unroll
            for (int np = 0; np < 4; ++np)
                ldsm_x4(bfr[0][4 * np], bfr[0][4 * np + 1],
                        bfr[0][4 * np + 2], bfr[0][4 * np + 3],
                        bBase + np * 16 * 432);
        }
#pragma unroll
        for (int ks = 0; ks < KSTEPS; ++ks) {
            const int cs = ks & 1, nx = cs ^ 1;
            if (ks + 1 < KSTEPS) {
                const uint32_t aA = aBase + (ks + 1) * 32;
                const uint32_t bA = bBase + (ks + 1) * 32;
                ldsm_x4(afr[nx][0], afr[nx][1], afr[nx][2], afr[nx][3], aA);
                ldsm_x4(afr[nx][4], afr[nx][5], afr[nx][6], afr[nx][7], aA + 16 * 432);
#pragma unroll
                for (int np = 0; np < 4; ++np)
                    ldsm_x4(bfr[nx][4 * np], bfr[nx][4 * np + 1],
                            bfr[nx][4 * np + 2], bfr[nx][4 * np + 3],
                            bA + np * 16 * 432);
            }
#pragma unroll
            for (int nt = 0; nt < 8; ++nt) {
                const uint32_t* bp = &bfr[cs][(nt >> 1) * 4 + (nt & 1) * 2];
                mma16816(dacc[0][nt], &afr[cs][0], bp);
                mma16816(dacc[1][nt], &afr[cs][4], bp);
            }
        }

        // ---- fold into per-point running max/max2 ----
#pragma unroll
        for (int mt = 0; mt < 2; ++mt)
#pragma unroll
            for (int nt = 0; nt < 8; ++nt) {
                int k0 = cb + wn * 64 + nt * 8 + 2 * (lane & 3);
#pragma unroll
                for (int c = 0; c < 4; ++c) {
                    int s = mt * 2 + (c >> 1);
                    float v = dacc[mt][nt][c];
                    int   k = k0 + (c & 1);
                    if (v > bestv[s]) { best2v[s] = bestv[s]; bestv[s] = v; bidx[s] = k; }
                    else if (v > best2v[s]) best2v[s] = v;
                }
            }

        if (ch + 1 < NCHUNK) {
            CP_WAIT0();
            __syncthreads();               // next B buffer resident & safe
        }
    }

    // ---- warp merge across the 4 lanes sharing each point ----
#pragma unroll
    for (int st = 1; st <= 2; st <<= 1) {
#pragma unroll
        for (int s = 0; s < 4; ++s) {
            float ob  = __shfl_xor_sync(0xFFFFFFFFu, bestv[s],  st);
            float ob2 = __shfl_xor_sync(0xFFFFFFFFu, best2v[s], st);
            int   oi  = __shfl_xor_sync(0xFFFFFFFFu, bidx[s],   st);
            if (ob > bestv[s]) {
                best2v[s] = fmaxf(bestv[s], ob2);
                bestv[s] = ob; bidx[s] = oi;
            } else {
                best2v[s] = fmaxf(best2v[s], ob);
            }
        }
    }
    if ((lane & 3) == 0) {
#pragma unroll
        for (int s = 0; s < 4; ++s) {
            int pt = wm * 32 + (lane >> 2) + s * 8;
            s_bm[wn * 128 + pt]  = bestv[s];
            s_b2m[wn * 128 + pt] = best2v[s];
            s_im[wn * 128 + pt]  = bidx[s];
        }
    }
    __syncthreads();

    // ---- final merge across the 2 warp columns, flag near-ties ----
    if (tid < MPTS) {
        float m0 = s_bm[tid],  m1 = s_bm[128 + tid];
        float q0 = s_b2m[tid], q1 = s_b2m[128 + tid];
        int   i0 = s_im[tid],  i1 = s_im[128 + tid];
        float mx, m2; int ix;
        if (m0 >= m1) { mx = m0; ix = i0; m2 = fmaxf(q0, m1); }
        else          { mx = m1; ix = i1; m2 = fmaxf(q1, m0); }
        s_fidx[tid] = ix;
        s_flag[tid] = (mx - m2 < MARGIN_D) ? 1 : 0;
    }
    __syncthreads();

    // ---- exact fp64 rescue for near-ties (block-parallel, rare) ----
    const float4* emb4 = reinterpret_cast<const float4*>(emb);
#pragma unroll 1
    for (int pt = 0; pt < MPTS; ++pt) {
        if (!s_flag[pt]) continue;        // uniform
        double bb = 1e300;
        int bi2 = 0;
#pragma unroll 1
        for (int q = 0; q < 4; ++q) {
            int k = tid * 4 + q;
            const float4* row = emb4 + (size_t)k * (Dm / 4);
            double ssum = 0.0;
#pragma unroll
            for (int jj = 0; jj < Dm / 4; ++jj) {
                float4 e = row[jj];
                double d0 = (double)z32[pt * 65 + 4 * jj]     - e.x;
                double d1 = (double)z32[pt * 65 + 4 * jj + 1] - e.y;
                double d2 = (double)z32[pt * 65 + 4 * jj + 2] - e.z;
                double d3 = (double)z32[pt * 65 + 4 * jj + 3] - e.w;
                ssum += d0 * d0 + d1 * d1 + d2 * d2 + d3 * d3;
            }
            if (ssum < bb) { bb = ssum; bi2 = k; }
        }
        s_rb[tid] = bb; s_ri[tid] = bi2;
        __syncthreads();
        for (int st = 128; st > 0; st >>= 1) {
            if (tid < st) {
                double o = s_rb[tid + st]; int oi = s_ri[tid + st];
                double m0 = s_rb[tid];     int mi = s_ri[tid];
                if (o < m0 || (o == m0 && oi < mi)) { s_rb[tid] = o; s_ri[tid] = oi; }
            }
            __syncthreads();
        }
        if (tid == 0) s_fidx[pt] = s_ri[0];
        __syncthreads();
    }
    __syncthreads();

    // ---- per-point outputs + EMA segment sums ----
    if (tid < MPTS) {
        int pt = tid, n = n0 + pt, idx = s_fidx[pt];
        g_indices[n] = idx;
        if (idx_out) idx_out[n] = (float)idx;
        atomicAdd(&g_counts[idx], 1.0f);
        float* dst = g_embed_sum + (size_t)idx * Dm;
#pragma unroll
        for (int j = 0; j < Dm / 4; ++j)
            red_add_v4(dst + 4 * j,
                       z32[pt * 65 + 4 * j],     z32[pt * 65 + 4 * j + 1],
                       z32[pt * 65 + 4 * j + 2], z32[pt * 65 + 4 * j + 3]);
    }
}

// ----------------- k_cluster ------------------------------------------------
__global__ void k_cluster(const float* __restrict__ cluster_size) {
    __shared__ float red[Km];
    int k = threadIdx.x;
    float ncs = fmaf(cluster_size[k], DECAY, (1.0f - DECAY) * g_counts[k]);
    red[k] = ncs;
    __syncthreads();
    for (int s = Km / 2; s > 0; s >>= 1) {
        if (k < s) red[k] += red[k + s];
        __syncthreads();
    }
    float n = red[0];
    g_smoothed[k] = __fmul_rn(__fdiv_rn(ncs + EPSm, n + (float)Km * EPSm), n);
}

// ----------------- k_embed --------------------------------------------------
__global__ void k_embed(const float* __restrict__ embed_avg) {
    int i = blockIdx.x * blockDim.x + threadIdx.x;
    float na = fmaf(embed_avg[i], DECAY, (1.0f - DECAY) * g_embed_sum[i]);
    g_new_embedding[i] = __fdiv_rn(na, g_smoothed[i >> 6]);
}

// ----------------- k_quant --------------------------------------------------
__global__ void __launch_bounds__(256)
k_quant(const float* __restrict__ z, float* __restrict__ out) {
    __shared__ float red[256];
    const int n = blockIdx.x * 256 + threadIdx.x;
    const int b = n >> 12;
    const int t = n & (Tm - 1);
    const float* zb = z + ((size_t)b * Dm) * Tm + t;
    float* ob = out + OFF_ZQ + ((size_t)b * Dm) * Tm + t;

    const int idx = g_indices[n];
    const float4* row = reinterpret_cast<const float4*>(g_new_embedding + (size_t)idx * Dm);

    float acc = 0.0f;
#pragma unroll
    for (int j = 0; j < Dm / 4; j++) {
        float4 e = row[j];
        float zv, df;
        zv = zb[(size_t)(4 * j + 0) * Tm]; ob[(size_t)(4 * j + 0) * Tm] = e.x; df = zv - e.x; acc = fmaf(df, df, acc);
        zv = zb[(size_t)(4 * j + 1) * Tm]; ob[(size_t)(4 * j + 1) * Tm] = e.y; df = zv - e.y; acc = fmaf(df, df, acc);
        zv = zb[(size_t)(4 * j + 2) * Tm]; ob[(size_t)(4 * j + 2) * Tm] = e.z; df = zv - e.z; acc = fmaf(df, df, acc);
        zv = zb[(size_t)(4 * j + 3) * Tm]; ob[(size_t)(4 * j + 3) * Tm] = e.w; df = zv - e.w; acc = fmaf(df, df, acc);
    }

    red[threadIdx.x] = acc;
    __syncthreads();
    for (int st = 128; st > 0; st >>= 1) {
        if (threadIdx.x < st) red[threadIdx.x] += red[threadIdx.x + st];
        __syncthreads();
    }
    if (threadIdx.x == 0) atomicAdd(&g_loss, red[0]);
}

// ----------------- k_final --------------------------------------------------
__global__ void k_final(float* __restrict__ loss_out) {
    loss_out[0] = 0.25f * __fdiv_rn(g_loss, (float)((size_t)Nm * Dm));
}

// ----------------- launch ----------------------------------------------------
extern "C" void kernel_launch(void* const* d_in, const int* in_sizes, int n_in,
                              void* d_out, int out_size) {
    const float* z    = (const float*)d_in[0];
    const float* emb  = (const float*)d_in[1];
    const float* cs   = (const float*)d_in[2];
    const float* avg  = (const float*)d_in[3];
    float* out = (float*)d_out;

    const bool full = ((size_t)out_size >= SZ_FULL);
    float* idx_out  = full ? out + OFF_IDX  : nullptr;
    float* loss_out = full ? out + OFF_LOSS : nullptr;

    cudaFuncSetAttribute(k_argmin, cudaFuncAttributeMaxDynamicSharedMemorySize, SMEM_SZ);

    k_zero1<<<Km * Dm / 2 / 1024, 1024>>>();
    k_zero2<<<(Km * Dm / 2 + Km + 1 + 1023) / 1024, 1024>>>();
    k_prep<<<Km / 256, 256>>>(emb);
    k_argmin<<<Nm / MPTS, 256, SMEM_SZ>>>(z, emb, idx_out);
    k_cluster<<<1, Km>>>(cs);
    k_embed<<<(Km * Dm) / 1024, 1024>>>(avg);
    k_quant<<<Nm / 256, 256>>>(z, out);
    if (loss_out) k_final<<<1, 1>>>(loss_out);
}